// round 1
// baseline (speedup 1.0000x reference)
#include <cuda_runtime.h>
#include <math.h>

#define NTOK 512
#define DIM 256
#define NH 8
#define HDIM 32
#define HIDN 682

// ---------------- scratch (device globals; no allocation) ----------------
__device__ float g_xn[NTOK*DIM];
__device__ float g_q[NTOK*DIM];
__device__ float g_kT[DIM*NTOK];
__device__ float g_v[NTOK*DIM];
__device__ float g_PbT[DIM*NTOK];     // [c][n]
__device__ float g_Pv[NTOK*DIM];      // [n][c]
__device__ float g_rv2T[DIM*DIM];     // [c][o]
__device__ float g_qkvT[DIM*3*DIM];   // [k][o]
__device__ float g_w1T[DIM*HIDN];     // [k][o]
__device__ float g_w2T[DIM*HIDN];
__device__ float g_w3T[HIDN*DIM];     // [o][d]
__device__ float g_scores[NH*NTOK*NTOK]; // 8MB
__device__ float g_resid[NTOK*DIM];
__device__ float g_xn2[NTOK*DIM];
__device__ float g_gate[NTOK*HIDN];

__device__ __forceinline__ float fsilu(float x) {
    float e = __expf(-x);
    return __fdividef(x, 1.0f + e);
}

// ---------------- prep: P matrices + transposes ----------------
__global__ void prep_kernel(const float* __restrict__ coords,
                            const float* __restrict__ rb1_w,
                            const float* __restrict__ rv1_w,
                            const float* __restrict__ qkv_w,
                            const float* __restrict__ rv2_w,
                            const float* __restrict__ w1,
                            const float* __restrict__ w2,
                            const float* __restrict__ w3) {
    int idx = blockIdx.x * blockDim.x + threadIdx.x;
    if (idx < NTOK*DIM) {
        int n = idx / DIM, c = idx % DIM;
        float x0 = coords[n*3+0], x1 = coords[n*3+1], x2 = coords[n*3+2];
        g_PbT[c*NTOK + n] = x0*rb1_w[c*3+0] + x1*rb1_w[c*3+1] + x2*rb1_w[c*3+2];
        g_Pv[idx]         = x0*rv1_w[c*3+0] + x1*rv1_w[c*3+1] + x2*rv1_w[c*3+2];
    }
    if (idx < 3*DIM*DIM) { int o = idx/DIM, k = idx%DIM; g_qkvT[k*(3*DIM)+o] = qkv_w[idx]; }
    if (idx < DIM*DIM)   { int o = idx/DIM, c = idx%DIM; g_rv2T[c*DIM+o]     = rv2_w[idx]; }
    if (idx < HIDN*DIM)  { int o = idx/DIM, k = idx%DIM; g_w1T[k*HIDN+o] = w1[idx]; g_w2T[k*HIDN+o] = w2[idx]; }
    if (idx < DIM*HIDN)  { int d = idx/HIDN, o = idx%HIDN; g_w3T[o*DIM+d] = w3[idx]; }
}

// ---------------- layernorm (block per row, 256 threads) ----------------
__global__ void ln_kernel(const float* __restrict__ xext,
                          const float* __restrict__ w,
                          const float* __restrict__ b,
                          int mode) {
    __shared__ float sb[8];
    const float* src = (mode == 0) ? xext : g_resid;
    float* dst = (mode == 0) ? g_xn : g_xn2;
    int i = blockIdx.x, t = threadIdx.x;
    float v = src[i*DIM + t];

    float s = v;
    #pragma unroll
    for (int o = 16; o; o >>= 1) s += __shfl_xor_sync(0xffffffffu, s, o);
    if ((t & 31) == 0) sb[t >> 5] = s;
    __syncthreads();
    if (t == 0) { float a = 0.f; for (int k = 0; k < 8; k++) a += sb[k]; sb[0] = a; }
    __syncthreads();
    float mean = sb[0] * (1.0f / DIM);
    __syncthreads();

    float d = v - mean;
    float q = d * d;
    #pragma unroll
    for (int o = 16; o; o >>= 1) q += __shfl_xor_sync(0xffffffffu, q, o);
    if ((t & 31) == 0) sb[t >> 5] = q;
    __syncthreads();
    if (t == 0) { float a = 0.f; for (int k = 0; k < 8; k++) a += sb[k]; sb[0] = a; }
    __syncthreads();
    float var = sb[0] * (1.0f / DIM);
    float inv = rsqrtf(var + 1e-5f);
    dst[i*DIM + t] = d * inv * w[t] + b[t];
}

// ---------------- QKV GEMM: 8 rows/block ----------------
__global__ __launch_bounds__(256) void qkv_kernel(const float* __restrict__ qkv_b) {
    __shared__ float xs[8][DIM];
    int i0 = blockIdx.x * 8, t = threadIdx.x;
    #pragma unroll
    for (int ii = 0; ii < 8; ii++) xs[ii][t] = g_xn[(i0+ii)*DIM + t];
    __syncthreads();
    float acc[8][3];
    #pragma unroll
    for (int ii = 0; ii < 8; ii++) { acc[ii][0] = 0.f; acc[ii][1] = 0.f; acc[ii][2] = 0.f; }
    for (int k = 0; k < DIM; k++) {
        float w0 = g_qkvT[k*768 + t];
        float w1 = g_qkvT[k*768 + t + 256];
        float w2 = g_qkvT[k*768 + t + 512];
        #pragma unroll
        for (int ii = 0; ii < 8; ii++) {
            float xv = xs[ii][k];
            acc[ii][0] += xv * w0;
            acc[ii][1] += xv * w1;
            acc[ii][2] += xv * w2;
        }
    }
    float bq = qkv_b[t], bk = qkv_b[256 + t], bv = qkv_b[512 + t];
    #pragma unroll
    for (int ii = 0; ii < 8; ii++) {
        g_q[(i0+ii)*DIM + t]   = acc[ii][0] + bq;
        g_kT[t*NTOK + (i0+ii)] = acc[ii][1] + bk;   // store k transposed
        g_v[(i0+ii)*DIM + t]   = acc[ii][2] + bv;
    }
}

// ---------------- scores = q.k/sqrt(hd) + rel_bias; 2 queries/block, thread=j ----------------
__global__ __launch_bounds__(512) void scores_kernel(const float* __restrict__ rb1_b,
                                                     const float* __restrict__ rb2_w,
                                                     const float* __restrict__ rb2_b) {
    __shared__ float pbi[2*DIM];
    __shared__ float qi[2*DIM];
    __shared__ float rb2s[NH*DIM];
    int i0 = blockIdx.x * 2, j = threadIdx.x;
    for (int idx = j; idx < 2*DIM; idx += 512) {
        int ii = idx >> 8, c = idx & 255;
        pbi[idx] = g_PbT[c*NTOK + (i0+ii)] + rb1_b[c]; // fold bias
        qi[idx]  = g_q[(i0+ii)*DIM + c];
    }
    for (int idx = j; idx < NH*DIM; idx += 512) rb2s[idx] = rb2_w[idx];
    __syncthreads();

    float accb[2][NH] = {};
    float accs[2][NH] = {};
    #pragma unroll
    for (int h = 0; h < NH; h++) {
        for (int c32 = 0; c32 < 32; c32++) {
            int c = h*32 + c32;
            float pbj = g_PbT[c*NTOK + j];
            float kj  = g_kT[c*NTOK + j];
            #pragma unroll
            for (int ii = 0; ii < 2; ii++) {
                float hb = fsilu(pbi[ii*DIM + c] - pbj);
                #pragma unroll
                for (int hh = 0; hh < NH; hh++)
                    accb[ii][hh] += hb * rb2s[hh*DIM + c];
                accs[ii][h] += qi[ii*DIM + c] * kj;
            }
        }
    }
    const float sc = 0.17677669529663687f; // 1/sqrt(32)
    #pragma unroll
    for (int ii = 0; ii < 2; ii++)
        #pragma unroll
        for (int h = 0; h < NH; h++)
            g_scores[h*NTOK*NTOK + (i0+ii)*NTOK + j] = accs[ii][h]*sc + accb[ii][h] + rb2_b[h];
}

// ---------------- attention: softmax + w@v + (w-weighted hid_v)@rv2 + residual ----------------
__global__ __launch_bounds__(256) void attn_kernel(const float* __restrict__ x,
                                                   const float* __restrict__ rv1_b,
                                                   const float* __restrict__ rv2_b) {
    __shared__ float ws[2*NH*NTOK]; // 32 KB: scores -> softmax weights -> (reused) Whid stage
    int i0 = blockIdx.x * 2, t = threadIdx.x;
    for (int idx = t; idx < 2*NH*NTOK; idx += 256) {
        int ii = idx >> 12, h = (idx >> 9) & 7, j = idx & 511;
        ws[idx] = g_scores[h*NTOK*NTOK + (i0+ii)*NTOK + j];
    }
    __syncthreads();

    // softmax: 16 rows, 8 warps, 2 rows each
    int wid = t >> 5, lane = t & 31;
    for (int r = wid; r < 16; r += 8) {
        float* row = ws + r*NTOK;
        float m = -1e30f;
        for (int jj = lane; jj < NTOK; jj += 32) m = fmaxf(m, row[jj]);
        #pragma unroll
        for (int o = 16; o; o >>= 1) m = fmaxf(m, __shfl_xor_sync(0xffffffffu, m, o));
        float s = 0.f;
        for (int jj = lane; jj < NTOK; jj += 32) { float e = __expf(row[jj] - m); row[jj] = e; s += e; }
        #pragma unroll
        for (int o = 16; o; o >>= 1) s += __shfl_xor_sync(0xffffffffu, s, o);
        float inv = __fdividef(1.0f, s);
        for (int jj = lane; jj < NTOK; jj += 32) row[jj] *= inv;
    }
    __syncthreads();

    float pvir[2];
    #pragma unroll
    for (int ii = 0; ii < 2; ii++) pvir[ii] = g_Pv[(i0+ii)*DIM + t] + rv1_b[t];

    float accW[2][NH] = {};
    float accC[2] = {};
    int hs = t >> 5; // this thread's (head, dim) = (t/32, t%32)
    for (int j = 0; j < NTOK; j++) {
        float pv = g_Pv[j*DIM + t];
        float vv = g_v[j*DIM + t];
        #pragma unroll
        for (int ii = 0; ii < 2; ii++) {
            float hv = fsilu(pvir[ii] - pv);
            #pragma unroll
            for (int h = 0; h < NH; h++)
                accW[ii][h] += ws[ii*4096 + h*NTOK + j] * hv;
            accC[ii] += ws[ii*4096 + hs*NTOK + j] * vv;
        }
    }
    __syncthreads();
    #pragma unroll
    for (int ii = 0; ii < 2; ii++)
        #pragma unroll
        for (int h = 0; h < NH; h++)
            ws[ii*2048 + h*DIM + t] = accW[ii][h]; // stage Whid[ii][h][c=t]
    __syncthreads();

    float accP[2] = {};
    for (int c = 0; c < DIM; c++) {
        float rv = g_rv2T[c*DIM + t];
        #pragma unroll
        for (int ii = 0; ii < 2; ii++)
            accP[ii] += ws[ii*2048 + hs*DIM + c] * rv;
    }
    float bb = rv2_b[t];
    #pragma unroll
    for (int ii = 0; ii < 2; ii++) {
        int i = i0 + ii;
        g_resid[i*DIM + t] = x[i*DIM + t] + accC[ii] + accP[ii] + bb;
    }
}

// ---------------- FFN up-proj (SwiGLU): 8 rows/block ----------------
__global__ __launch_bounds__(256) void ffn1_kernel(const float* __restrict__ b1,
                                                   const float* __restrict__ b2) {
    __shared__ float xs[8][DIM];
    int i0 = blockIdx.x * 8, t = threadIdx.x;
    #pragma unroll
    for (int ii = 0; ii < 8; ii++) xs[ii][t] = g_xn2[(i0+ii)*DIM + t];
    __syncthreads();
    float a1[8][3] = {}, a2[8][3] = {};
    bool m2 = (t < HIDN - 512);
    for (int k = 0; k < DIM; k++) {
        float u0 = g_w1T[k*HIDN + t];
        float u1 = g_w1T[k*HIDN + t + 256];
        float u2 = m2 ? g_w1T[k*HIDN + t + 512] : 0.f;
        float v0 = g_w2T[k*HIDN + t];
        float v1 = g_w2T[k*HIDN + t + 256];
        float v2 = m2 ? g_w2T[k*HIDN + t + 512] : 0.f;
        #pragma unroll
        for (int ii = 0; ii < 8; ii++) {
            float xv = xs[ii][k];
            a1[ii][0] += xv*u0; a1[ii][1] += xv*u1; a1[ii][2] += xv*u2;
            a2[ii][0] += xv*v0; a2[ii][1] += xv*v1; a2[ii][2] += xv*v2;
        }
    }
    #pragma unroll
    for (int m = 0; m < 3; m++) {
        int o = t + m*256;
        if (o < HIDN) {
            float bb1 = b1[o], bb2 = b2[o];
            #pragma unroll
            for (int ii = 0; ii < 8; ii++)
                g_gate[(i0+ii)*HIDN + o] = fsilu(a1[ii][m] + bb1) * (a2[ii][m] + bb2);
        }
    }
}

// ---------------- FFN down-proj + residual ----------------
__global__ __launch_bounds__(256) void ffn2_kernel(const float* __restrict__ b3,
                                                   float* __restrict__ out) {
    __shared__ float gs[8*HIDN];
    int i0 = blockIdx.x * 8, t = threadIdx.x;
    for (int idx = t; idx < 8*HIDN; idx += 256) {
        int ii = idx / HIDN, o = idx % HIDN;
        gs[idx] = g_gate[(i0+ii)*HIDN + o];
    }
    __syncthreads();
    float acc[8] = {};
    for (int o = 0; o < HIDN; o++) {
        float w3v = g_w3T[o*DIM + t];
        #pragma unroll
        for (int ii = 0; ii < 8; ii++) acc[ii] += gs[ii*HIDN + o] * w3v;
    }
    float bb = b3[t];
    #pragma unroll
    for (int ii = 0; ii < 8; ii++) {
        int i = i0 + ii;
        out[i*DIM + t] = g_resid[i*DIM + t] + acc[ii] + bb;
    }
}

// ---------------- launch ----------------
extern "C" void kernel_launch(void* const* d_in, const int* in_sizes, int n_in,
                              void* d_out, int out_size) {
    const float* x      = (const float*)d_in[0];
    const float* coords = (const float*)d_in[1];
    const float* ln1_w  = (const float*)d_in[2];
    const float* ln1_b  = (const float*)d_in[3];
    const float* ln2_w  = (const float*)d_in[4];
    const float* ln2_b  = (const float*)d_in[5];
    const float* qkv_w  = (const float*)d_in[6];
    const float* qkv_b  = (const float*)d_in[7];
    const float* rb1_w  = (const float*)d_in[8];
    const float* rb1_b  = (const float*)d_in[9];
    const float* rb2_w  = (const float*)d_in[10];
    const float* rb2_b  = (const float*)d_in[11];
    const float* rv1_w  = (const float*)d_in[12];
    const float* rv1_b  = (const float*)d_in[13];
    const float* rv2_w  = (const float*)d_in[14];
    const float* rv2_b  = (const float*)d_in[15];
    const float* w1     = (const float*)d_in[16];
    const float* b1     = (const float*)d_in[17];
    const float* w2     = (const float*)d_in[18];
    const float* b2     = (const float*)d_in[19];
    const float* w3     = (const float*)d_in[20];
    const float* b3     = (const float*)d_in[21];
    float* out = (float*)d_out;

    prep_kernel<<<768, 256>>>(coords, rb1_w, rv1_w, qkv_w, rv2_w, w1, w2, w3);
    ln_kernel<<<NTOK, 256>>>(x, ln1_w, ln1_b, 0);
    qkv_kernel<<<NTOK/8, 256>>>(qkv_b);
    scores_kernel<<<NTOK/2, 512>>>(rb1_b, rb2_w, rb2_b);
    attn_kernel<<<NTOK/2, 256>>>(x, rv1_b, rv2_b);
    ln_kernel<<<NTOK, 256>>>(x, ln2_w, ln2_b, 1);
    ffn1_kernel<<<NTOK/8, 256>>>(b1, b2);
    ffn2_kernel<<<NTOK/8, 256>>>(b3, out);
}

// round 2
// speedup vs baseline: 1.3984x; 1.3984x over previous
#include <cuda_runtime.h>
#include <math.h>

#define NTOK 512
#define DIM 256
#define NH 8
#define HDIM 32
#define HIDN 682

// ---------------- scratch (device globals; no allocation) ----------------
__device__ float g_xn[NTOK*DIM];
__device__ float g_q[NTOK*DIM];
__device__ float g_kT[DIM*NTOK];
__device__ float g_v[NTOK*DIM];
__device__ float g_PbT[DIM*NTOK];     // [c][n]
__device__ float g_Pv[NTOK*DIM];      // [n][c]
__device__ float g_rv2T[DIM*DIM];     // [c][o]
__device__ float g_rb2T[DIM*NH];      // [c][h]
__device__ float g_qkvT[DIM*3*DIM];   // [k][o]
__device__ float g_w1T[DIM*HIDN];     // [k][o]
__device__ float g_w2T[DIM*HIDN];
__device__ float g_w3T[HIDN*DIM];     // [o][d]
__device__ float g_scores[NTOK*NH*NTOK]; // [i][h][j], 8MB
__device__ float g_resid[NTOK*DIM];
__device__ float g_xn2[NTOK*DIM];
__device__ float g_gate[NTOK*HIDN];

__device__ __forceinline__ float fsilu(float x) {
    float e = __expf(-x);
    return __fdividef(x, 1.0f + e);
}

// ---------------- prep: P matrices + transposes ----------------
__global__ void prep_kernel(const float* __restrict__ coords,
                            const float* __restrict__ rb1_w,
                            const float* __restrict__ rv1_w,
                            const float* __restrict__ qkv_w,
                            const float* __restrict__ rv2_w,
                            const float* __restrict__ rb2_w,
                            const float* __restrict__ w1,
                            const float* __restrict__ w2,
                            const float* __restrict__ w3) {
    int idx = blockIdx.x * blockDim.x + threadIdx.x;
    if (idx < NTOK*DIM) {
        int n = idx / DIM, c = idx % DIM;
        float x0 = coords[n*3+0], x1 = coords[n*3+1], x2 = coords[n*3+2];
        g_PbT[c*NTOK + n] = x0*rb1_w[c*3+0] + x1*rb1_w[c*3+1] + x2*rb1_w[c*3+2];
        g_Pv[idx]         = x0*rv1_w[c*3+0] + x1*rv1_w[c*3+1] + x2*rv1_w[c*3+2];
    }
    if (idx < 3*DIM*DIM) { int o = idx/DIM, k = idx%DIM; g_qkvT[k*(3*DIM)+o] = qkv_w[idx]; }
    if (idx < DIM*DIM)   { int o = idx/DIM, c = idx%DIM; g_rv2T[c*DIM+o]     = rv2_w[idx]; }
    if (idx < NH*DIM)    { int h = idx/DIM, c = idx%DIM; g_rb2T[c*NH+h]      = rb2_w[idx]; }
    if (idx < HIDN*DIM)  { int o = idx/DIM, k = idx%DIM; g_w1T[k*HIDN+o] = w1[idx]; g_w2T[k*HIDN+o] = w2[idx]; }
    if (idx < DIM*HIDN)  { int d = idx/HIDN, o = idx%HIDN; g_w3T[o*DIM+d] = w3[idx]; }
}

// ---------------- layernorm (block per row, 256 threads) ----------------
__global__ void ln_kernel(const float* __restrict__ xext,
                          const float* __restrict__ w,
                          const float* __restrict__ b,
                          int mode) {
    __shared__ float sb[8];
    const float* src = (mode == 0) ? xext : g_resid;
    float* dst = (mode == 0) ? g_xn : g_xn2;
    int i = blockIdx.x, t = threadIdx.x;
    float v = src[i*DIM + t];

    float s = v;
    #pragma unroll
    for (int o = 16; o; o >>= 1) s += __shfl_xor_sync(0xffffffffu, s, o);
    if ((t & 31) == 0) sb[t >> 5] = s;
    __syncthreads();
    if (t == 0) { float a = 0.f; for (int k = 0; k < 8; k++) a += sb[k]; sb[0] = a; }
    __syncthreads();
    float mean = sb[0] * (1.0f / DIM);
    __syncthreads();

    float d = v - mean;
    float q = d * d;
    #pragma unroll
    for (int o = 16; o; o >>= 1) q += __shfl_xor_sync(0xffffffffu, q, o);
    if ((t & 31) == 0) sb[t >> 5] = q;
    __syncthreads();
    if (t == 0) { float a = 0.f; for (int k = 0; k < 8; k++) a += sb[k]; sb[0] = a; }
    __syncthreads();
    float var = sb[0] * (1.0f / DIM);
    float inv = rsqrtf(var + 1e-5f);
    dst[i*DIM + t] = d * inv * w[t] + b[t];
}

// ---------------- QKV GEMM: 4 rows x 256-out chunk per block ----------------
__global__ __launch_bounds__(256) void qkv_kernel(const float* __restrict__ qkv_b) {
    __shared__ float xs[DIM][4];
    int i0 = blockIdx.x * 4, chunk = blockIdx.y, t = threadIdx.x;
    #pragma unroll
    for (int r = 0; r < 4; r++) xs[t][r] = g_xn[(i0+r)*DIM + t];
    __syncthreads();
    float acc[4] = {};
    int ob = chunk*256 + t;
    #pragma unroll 4
    for (int k = 0; k < DIM; k++) {
        float w = g_qkvT[k*768 + ob];
        float4 xv = *(float4*)xs[k];
        acc[0] += xv.x * w; acc[1] += xv.y * w;
        acc[2] += xv.z * w; acc[3] += xv.w * w;
    }
    float bb = qkv_b[ob];
    if (chunk == 0) {
        #pragma unroll
        for (int r = 0; r < 4; r++) g_q[(i0+r)*DIM + t] = acc[r] + bb;
    } else if (chunk == 1) {
        #pragma unroll
        for (int r = 0; r < 4; r++) g_kT[t*NTOK + i0 + r] = acc[r] + bb;
    } else {
        #pragma unroll
        for (int r = 0; r < 4; r++) g_v[(i0+r)*DIM + t] = acc[r] + bb;
    }
}

// ---------------- scores = q.k/sqrt(hd) + rel_bias; 2 queries, 256 j per block ----------------
__global__ __launch_bounds__(256) void scores_kernel(const float* __restrict__ rb1_b,
                                                     const float* __restrict__ rb2_b) {
    __shared__ float pbq[DIM][4];   // {pb_i0+b, pb_i1+b, q_i0, q_i1}
    __shared__ float rb2s[DIM][8];
    int ib = blockIdx.x >> 1;
    int i0 = ib * 2;
    int t = threadIdx.x;
    int j = (blockIdx.x & 1) * 256 + t;

    pbq[t][0] = g_PbT[t*NTOK + i0]     + rb1_b[t];
    pbq[t][1] = g_PbT[t*NTOK + i0 + 1] + rb1_b[t];
    pbq[t][2] = g_q[i0*DIM + t];
    pbq[t][3] = g_q[(i0+1)*DIM + t];
    #pragma unroll
    for (int h = 0; h < 8; h++) rb2s[t][h] = g_rb2T[t*NH + h];
    __syncthreads();

    float accb[2][NH] = {};
    float accs[2][NH] = {};
    #pragma unroll
    for (int h = 0; h < NH; h++) {
        float qk0 = 0.f, qk1 = 0.f;
        #pragma unroll 4
        for (int c32 = 0; c32 < 32; c32++) {
            int c = h*32 + c32;
            float pbj = g_PbT[c*NTOK + j];
            float kj  = g_kT[c*NTOK + j];
            float4 pq = *(float4*)pbq[c];
            float hb0 = fsilu(pq.x - pbj);
            float hb1 = fsilu(pq.y - pbj);
            qk0 += pq.z * kj;
            qk1 += pq.w * kj;
            float rr[8];
            *(float4*)(rr)   = *(float4*)&rb2s[c][0];
            *(float4*)(rr+4) = *(float4*)&rb2s[c][4];
            #pragma unroll
            for (int hh = 0; hh < 8; hh++) {
                accb[0][hh] += hb0 * rr[hh];
                accb[1][hh] += hb1 * rr[hh];
            }
        }
        accs[0][h] = qk0; accs[1][h] = qk1;
    }
    const float sc = 0.17677669529663687f; // 1/sqrt(32)
    #pragma unroll
    for (int h = 0; h < NH; h++) {
        g_scores[(i0*NH + h)*NTOK + j]     = accs[0][h]*sc + accb[0][h] + rb2_b[h];
        g_scores[((i0+1)*NH + h)*NTOK + j] = accs[1][h]*sc + accb[1][h] + rb2_b[h];
    }
}

// ---------------- attention: softmax + w@v + (w-weighted hid_v)@rv2 + residual ----------------
__global__ __launch_bounds__(256) void attn_kernel(const float* __restrict__ x,
                                                   const float* __restrict__ rv1_b,
                                                   const float* __restrict__ rv2_b) {
    __shared__ float wT[NTOK*12];     // wT[j][h], padded to 12
    __shared__ float whid[NH*DIM];
    __shared__ float sinv[NH];
    int i = blockIdx.x, t = threadIdx.x;
    int wid = t >> 5, lane = t & 31;

    // softmax (unnormalized exp) for row h = wid; store transposed
    {
        const float* row = g_scores + (i*NH + wid)*NTOK;
        float m = -1e30f;
        for (int jj = lane; jj < NTOK; jj += 32) m = fmaxf(m, row[jj]);
        #pragma unroll
        for (int o = 16; o; o >>= 1) m = fmaxf(m, __shfl_xor_sync(0xffffffffu, m, o));
        float s = 0.f;
        for (int jj = lane; jj < NTOK; jj += 32) {
            float e = __expf(row[jj] - m);
            wT[jj*12 + wid] = e;
            s += e;
        }
        #pragma unroll
        for (int o = 16; o; o >>= 1) s += __shfl_xor_sync(0xffffffffu, s, o);
        if (lane == 0) sinv[wid] = __fdividef(1.0f, s);
    }
    __syncthreads();

    float pvi = g_Pv[i*DIM + t] + rv1_b[t];
    int hs = t >> 5;
    float accW[NH] = {};
    float accC = 0.f;
    #pragma unroll 2
    for (int j = 0; j < NTOK; j++) {
        float pv = g_Pv[j*DIM + t];
        float vv = g_v[j*DIM + t];
        float wr[8];
        *(float4*)(wr)   = *(float4*)&wT[j*12];
        *(float4*)(wr+4) = *(float4*)&wT[j*12 + 4];
        float hv = fsilu(pvi - pv);
        #pragma unroll
        for (int h = 0; h < 8; h++) accW[h] += wr[h] * hv;
        accC += wT[j*12 + hs] * vv;   // uniform-index LDS broadcast
    }
    __syncthreads();  // done reading wT region? whid is separate, but sync orders sinv reads too
    #pragma unroll
    for (int h = 0; h < 8; h++) whid[h*DIM + t] = accW[h] * sinv[h];
    accC *= sinv[hs];
    __syncthreads();

    float accP = 0.f;
    #pragma unroll 4
    for (int c = 0; c < DIM; c++)
        accP += whid[hs*DIM + c] * g_rv2T[c*DIM + t];

    g_resid[i*DIM + t] = x[i*DIM + t] + accC + accP + rv2_b[t];
}

// ---------------- FFN up-proj (SwiGLU): 4 rows x 256-out chunk ----------------
__global__ __launch_bounds__(256) void ffn1_kernel(const float* __restrict__ b1,
                                                   const float* __restrict__ b2) {
    __shared__ float xs[DIM][4];
    int i0 = blockIdx.x * 4, t = threadIdx.x;
    int o = blockIdx.y * 256 + t;
    #pragma unroll
    for (int r = 0; r < 4; r++) xs[t][r] = g_xn2[(i0+r)*DIM + t];
    __syncthreads();
    if (o >= HIDN) return;
    float a1[4] = {}, a2[4] = {};
    #pragma unroll 4
    for (int k = 0; k < DIM; k++) {
        float u = g_w1T[k*HIDN + o];
        float v = g_w2T[k*HIDN + o];
        float4 xv = *(float4*)xs[k];
        a1[0] += xv.x*u; a1[1] += xv.y*u; a1[2] += xv.z*u; a1[3] += xv.w*u;
        a2[0] += xv.x*v; a2[1] += xv.y*v; a2[2] += xv.z*v; a2[3] += xv.w*v;
    }
    float bb1 = b1[o], bb2 = b2[o];
    #pragma unroll
    for (int r = 0; r < 4; r++)
        g_gate[(i0+r)*HIDN + o] = fsilu(a1[r] + bb1) * (a2[r] + bb2);
}

// ---------------- FFN down-proj + residual: 2 rows per block ----------------
__global__ __launch_bounds__(256) void ffn2_kernel(const float* __restrict__ b3,
                                                   float* __restrict__ out) {
    __shared__ float gs[HIDN*2];      // gs[o][2]
    int i0 = blockIdx.x * 2, t = threadIdx.x;
    for (int idx = t; idx < HIDN*2; idx += 256) {
        int o = idx >> 1, ii = idx & 1;
        gs[idx] = g_gate[(i0+ii)*HIDN + o];
    }
    __syncthreads();
    float acc0 = 0.f, acc1 = 0.f;
    #pragma unroll 2
    for (int o = 0; o < HIDN; o++) {
        float w3v = g_w3T[o*DIM + t];
        float2 g2 = *(float2*)&gs[o*2];
        acc0 += g2.x * w3v;
        acc1 += g2.y * w3v;
    }
    float bb = b3[t];
    out[i0*DIM + t]     = g_resid[i0*DIM + t]     + acc0 + bb;
    out[(i0+1)*DIM + t] = g_resid[(i0+1)*DIM + t] + acc1 + bb;
}

// ---------------- launch ----------------
extern "C" void kernel_launch(void* const* d_in, const int* in_sizes, int n_in,
                              void* d_out, int out_size) {
    const float* x      = (const float*)d_in[0];
    const float* coords = (const float*)d_in[1];
    const float* ln1_w  = (const float*)d_in[2];
    const float* ln1_b  = (const float*)d_in[3];
    const float* ln2_w  = (const float*)d_in[4];
    const float* ln2_b  = (const float*)d_in[5];
    const float* qkv_w  = (const float*)d_in[6];
    const float* qkv_b  = (const float*)d_in[7];
    const float* rb1_w  = (const float*)d_in[8];
    const float* rb1_b  = (const float*)d_in[9];
    const float* rb2_w  = (const float*)d_in[10];
    const float* rb2_b  = (const float*)d_in[11];
    const float* rv1_w  = (const float*)d_in[12];
    const float* rv1_b  = (const float*)d_in[13];
    const float* rv2_w  = (const float*)d_in[14];
    const float* rv2_b  = (const float*)d_in[15];
    const float* w1     = (const float*)d_in[16];
    const float* b1     = (const float*)d_in[17];
    const float* w2     = (const float*)d_in[18];
    const float* b2     = (const float*)d_in[19];
    const float* w3     = (const float*)d_in[20];
    const float* b3     = (const float*)d_in[21];
    float* out = (float*)d_out;

    prep_kernel<<<768, 256>>>(coords, rb1_w, rv1_w, qkv_w, rv2_w, rb2_w, w1, w2, w3);
    ln_kernel<<<NTOK, 256>>>(x, ln1_w, ln1_b, 0);
    qkv_kernel<<<dim3(128, 3), 256>>>(qkv_b);
    scores_kernel<<<NTOK, 256>>>(rb1_b, rb2_b);
    attn_kernel<<<NTOK, 256>>>(x, rv1_b, rv2_b);
    ln_kernel<<<NTOK, 256>>>(x, ln2_w, ln2_b, 1);
    ffn1_kernel<<<dim3(128, 3), 256>>>(b1, b2);
    ffn2_kernel<<<256, 256>>>(b3, out);
}

// round 3
// speedup vs baseline: 1.5842x; 1.1329x over previous
#include <cuda_runtime.h>
#include <math.h>

#define NTOK 512
#define DIM 256
#define NH 8
#define HDIM 32
#define HIDN 682

typedef unsigned long long u64;

__device__ __forceinline__ u64 pk2(float lo, float hi) {
    u64 r; asm("mov.b64 %0, {%1,%2};" : "=l"(r) : "f"(lo), "f"(hi)); return r;
}
__device__ __forceinline__ float2 up2(u64 v) {
    float2 f; asm("mov.b64 {%0,%1}, %2;" : "=f"(f.x), "=f"(f.y) : "l"(v)); return f;
}
__device__ __forceinline__ u64 fma2(u64 a, u64 b, u64 c) {
    u64 d; asm("fma.rn.f32x2 %0, %1, %2, %3;" : "=l"(d) : "l"(a), "l"(b), "l"(c)); return d;
}
// silu via tanh: x*sigmoid(x) = h + h*tanh(h), h = x/2.  1 MUFU instead of 2.
__device__ __forceinline__ float fsilu(float x) {
    float h = 0.5f * x, t;
    asm("tanh.approx.f32 %0, %1;" : "=f"(t) : "f"(h));
    return fmaf(h, t, h);
}

// ---------------- scratch ----------------
__device__ float g_xn[NTOK*DIM];
__device__ float g_q[NTOK*DIM];
__device__ float g_kT[DIM*NTOK];
__device__ float g_v[NTOK*DIM];
__device__ float g_PbT[DIM*NTOK];     // [c][n]
__device__ float g_Pv[NTOK*DIM];      // [n][c]
__device__ float g_rv2T[DIM*DIM];     // [c][o]
__device__ float g_rb2T[DIM*NH];      // [c][h]
__device__ float g_qkvT[DIM*3*DIM];   // [k][o]
__device__ float g_w1T[DIM*HIDN];     // [k][o]
__device__ float g_w2T[DIM*HIDN];
__device__ float g_w3T[HIDN*DIM];     // [o][d]
__device__ float g_scores[NTOK*NH*NTOK]; // [i][h][j]
__device__ float g_resid[NTOK*DIM];
__device__ float g_xn2[NTOK*DIM];
__device__ float g_gate[NTOK*HIDN];

// ---------------- prep ----------------
__global__ void prep_kernel(const float* __restrict__ coords,
                            const float* __restrict__ rb1_w,
                            const float* __restrict__ rv1_w,
                            const float* __restrict__ qkv_w,
                            const float* __restrict__ rv2_w,
                            const float* __restrict__ rb2_w,
                            const float* __restrict__ w1,
                            const float* __restrict__ w2,
                            const float* __restrict__ w3) {
    int idx = blockIdx.x * blockDim.x + threadIdx.x;
    if (idx < NTOK*DIM) {
        { // PbT coalesced: idx = c*NTOK + n
            int c = idx / NTOK, n = idx % NTOK;
            float x0 = coords[n*3+0], x1 = coords[n*3+1], x2 = coords[n*3+2];
            g_PbT[idx] = x0*rb1_w[c*3+0] + x1*rb1_w[c*3+1] + x2*rb1_w[c*3+2];
        }
        { // Pv: idx = n*DIM + c
            int n = idx / DIM, c = idx % DIM;
            float x0 = coords[n*3+0], x1 = coords[n*3+1], x2 = coords[n*3+2];
            g_Pv[idx] = x0*rv1_w[c*3+0] + x1*rv1_w[c*3+1] + x2*rv1_w[c*3+2];
        }
    }
    if (idx < 3*DIM*DIM) { int o = idx/DIM, k = idx%DIM; g_qkvT[k*(3*DIM)+o] = qkv_w[idx]; }
    if (idx < DIM*DIM)   { int o = idx/DIM, c = idx%DIM; g_rv2T[c*DIM+o]     = rv2_w[idx]; }
    if (idx < NH*DIM)    { int h = idx/DIM, c = idx%DIM; g_rb2T[c*NH+h]      = rb2_w[idx]; }
    if (idx < HIDN*DIM)  { int o = idx/DIM, k = idx%DIM; g_w1T[k*HIDN+o] = w1[idx]; g_w2T[k*HIDN+o] = w2[idx]; }
    if (idx < DIM*HIDN)  { int d = idx/HIDN, o = idx%HIDN; g_w3T[o*DIM+d] = w3[idx]; }
}

// ---------------- layernorm ----------------
__global__ void ln_kernel(const float* __restrict__ xext,
                          const float* __restrict__ w,
                          const float* __restrict__ b,
                          int mode) {
    __shared__ float sb[8];
    const float* src = (mode == 0) ? xext : g_resid;
    float* dst = (mode == 0) ? g_xn : g_xn2;
    int i = blockIdx.x, t = threadIdx.x;
    float v = src[i*DIM + t];

    float s = v;
    #pragma unroll
    for (int o = 16; o; o >>= 1) s += __shfl_xor_sync(0xffffffffu, s, o);
    if ((t & 31) == 0) sb[t >> 5] = s;
    __syncthreads();
    if (t == 0) { float a = 0.f; for (int k = 0; k < 8; k++) a += sb[k]; sb[0] = a; }
    __syncthreads();
    float mean = sb[0] * (1.0f / DIM);
    __syncthreads();

    float d = v - mean;
    float q = d * d;
    #pragma unroll
    for (int o = 16; o; o >>= 1) q += __shfl_xor_sync(0xffffffffu, q, o);
    if ((t & 31) == 0) sb[t >> 5] = q;
    __syncthreads();
    if (t == 0) { float a = 0.f; for (int k = 0; k < 8; k++) a += sb[k]; sb[0] = a; }
    __syncthreads();
    float var = sb[0] * (1.0f / DIM);
    float inv = rsqrtf(var + 1e-5f);
    dst[i*DIM + t] = d * inv * w[t] + b[t];
}

// ---------------- QKV GEMM: 4 rows x 256-out chunk, packed ----------------
__global__ __launch_bounds__(256) void qkv_kernel(const float* __restrict__ qkv_b) {
    __shared__ float4 xs[DIM];
    int i0 = blockIdx.x * 4, chunk = blockIdx.y, t = threadIdx.x;
    xs[t] = make_float4(g_xn[i0*DIM+t], g_xn[(i0+1)*DIM+t],
                        g_xn[(i0+2)*DIM+t], g_xn[(i0+3)*DIM+t]);
    __syncthreads();
    int ob = chunk*256 + t;
    u64 acc01 = 0, acc23 = 0;
    #pragma unroll 4
    for (int k = 0; k < DIM; k++) {
        float w = g_qkvT[k*768 + ob];
        ulonglong2 xv = *(const ulonglong2*)&xs[k];
        u64 ww = pk2(w, w);
        acc01 = fma2(xv.x, ww, acc01);
        acc23 = fma2(xv.y, ww, acc23);
    }
    float bb = qkv_b[ob];
    float2 a = up2(acc01), c = up2(acc23);
    float r[4] = { a.x+bb, a.y+bb, c.x+bb, c.y+bb };
    if (chunk == 0) {
        #pragma unroll
        for (int rr = 0; rr < 4; rr++) g_q[(i0+rr)*DIM + t] = r[rr];
    } else if (chunk == 1) {
        #pragma unroll
        for (int rr = 0; rr < 4; rr++) g_kT[t*NTOK + i0 + rr] = r[rr];
    } else {
        #pragma unroll
        for (int rr = 0; rr < 4; rr++) g_v[(i0+rr)*DIM + t] = r[rr];
    }
}

// ---------------- scores: 2 queries x 256 j per block, packed ----------------
__global__ __launch_bounds__(256, 4) void scores_kernel(const float* __restrict__ rb1_b,
                                                        const float* __restrict__ rb2_b) {
    __shared__ float2 pb2[DIM];
    __shared__ float2 q2[DIM];
    __shared__ float rb2s[DIM][8];
    int i0 = (blockIdx.x >> 1) * 2;
    int t = threadIdx.x;
    int j = (blockIdx.x & 1) * 256 + t;

    float bb = rb1_b[t];
    pb2[t] = make_float2(g_PbT[t*NTOK + i0] + bb, g_PbT[t*NTOK + i0 + 1] + bb);
    q2[t]  = make_float2(g_q[i0*DIM + t], g_q[(i0+1)*DIM + t]);
    #pragma unroll
    for (int h = 0; h < 8; h++) rb2s[t][h] = g_rb2T[t*NH + h];
    __syncthreads();

    u64 accb0[4] = {}, accb1[4] = {}, accs[8] = {};
    #pragma unroll
    for (int h = 0; h < NH; h++) {
        #pragma unroll 4
        for (int c32 = 0; c32 < 32; c32++) {
            int c = h*32 + c32;
            float pbj = g_PbT[c*NTOK + j];
            float kj  = g_kT[c*NTOK + j];
            u64 pb01 = *(const u64*)&pb2[c];
            u64 q01  = *(const u64*)&q2[c];
            float2 pb = up2(pb01);
            float hb0 = fsilu(pb.x - pbj);
            float hb1 = fsilu(pb.y - pbj);
            u64 h00 = pk2(hb0, hb0), h11 = pk2(hb1, hb1);
            ulonglong2 rA = *(const ulonglong2*)&rb2s[c][0];
            ulonglong2 rB = *(const ulonglong2*)&rb2s[c][4];
            accb0[0] = fma2(h00, rA.x, accb0[0]); accb0[1] = fma2(h00, rA.y, accb0[1]);
            accb0[2] = fma2(h00, rB.x, accb0[2]); accb0[3] = fma2(h00, rB.y, accb0[3]);
            accb1[0] = fma2(h11, rA.x, accb1[0]); accb1[1] = fma2(h11, rA.y, accb1[1]);
            accb1[2] = fma2(h11, rB.x, accb1[2]); accb1[3] = fma2(h11, rB.y, accb1[3]);
            accs[h]  = fma2(q01, pk2(kj, kj), accs[h]);
        }
    }
    const float sc = 0.17677669529663687f;
    float b0[8], b1[8];
    #pragma unroll
    for (int hp = 0; hp < 4; hp++) {
        float2 v0 = up2(accb0[hp]); b0[2*hp] = v0.x; b0[2*hp+1] = v0.y;
        float2 v1 = up2(accb1[hp]); b1[2*hp] = v1.x; b1[2*hp+1] = v1.y;
    }
    #pragma unroll
    for (int h = 0; h < NH; h++) {
        float2 qk = up2(accs[h]);
        float rbb = rb2_b[h];
        g_scores[(i0*NH + h)*NTOK + j]     = qk.x*sc + b0[h] + rbb;
        g_scores[((i0+1)*NH + h)*NTOK + j] = qk.y*sc + b1[h] + rbb;
    }
}

// ---------------- attention ----------------
__global__ __launch_bounds__(256, 4) void attn_kernel(const float* __restrict__ x,
                                                      const float* __restrict__ rv1_b,
                                                      const float* __restrict__ rv2_b) {
    __shared__ float wT[NTOK*12];     // wT[j][h], padded to 12
    __shared__ float whid[NH*DIM];
    __shared__ float sinv[NH];
    int i = blockIdx.x, t = threadIdx.x;
    int wid = t >> 5, lane = t & 31;

    { // softmax (unnormalized) for head h = wid, stored transposed
        const float* row = g_scores + (i*NH + wid)*NTOK;
        float m = -1e30f;
        for (int jj = lane; jj < NTOK; jj += 32) m = fmaxf(m, row[jj]);
        #pragma unroll
        for (int o = 16; o; o >>= 1) m = fmaxf(m, __shfl_xor_sync(0xffffffffu, m, o));
        float s = 0.f;
        for (int jj = lane; jj < NTOK; jj += 32) {
            float e = __expf(row[jj] - m);
            wT[jj*12 + wid] = e;
            s += e;
        }
        #pragma unroll
        for (int o = 16; o; o >>= 1) s += __shfl_xor_sync(0xffffffffu, s, o);
        if (lane == 0) sinv[wid] = __fdividef(1.0f, s);
    }
    __syncthreads();

    float pvi = g_Pv[i*DIM + t] + rv1_b[t];
    int hs = t >> 5;
    u64 accW[4] = {};
    float accC = 0.f;
    #pragma unroll 2
    for (int j = 0; j < NTOK; j++) {
        float pv = g_Pv[j*DIM + t];
        float vv = g_v[j*DIM + t];
        ulonglong2 wA = *(const ulonglong2*)&wT[j*12];
        ulonglong2 wB = *(const ulonglong2*)&wT[j*12 + 4];
        float hv = fsilu(pvi - pv);
        u64 hh = pk2(hv, hv);
        accW[0] = fma2(hh, wA.x, accW[0]); accW[1] = fma2(hh, wA.y, accW[1]);
        accW[2] = fma2(hh, wB.x, accW[2]); accW[3] = fma2(hh, wB.y, accW[3]);
        accC += wT[j*12 + hs] * vv;  // warp-uniform LDS broadcast
    }
    #pragma unroll
    for (int hp = 0; hp < 4; hp++) {
        float2 v = up2(accW[hp]);
        whid[(2*hp)*DIM + t]   = v.x * sinv[2*hp];
        whid[(2*hp+1)*DIM + t] = v.y * sinv[2*hp+1];
    }
    accC *= sinv[hs];
    __syncthreads();

    float accP = 0.f;
    #pragma unroll 4
    for (int c = 0; c < DIM; c++)
        accP += whid[hs*DIM + c] * g_rv2T[c*DIM + t];

    g_resid[i*DIM + t] = x[i*DIM + t] + accC + accP + rv2_b[t];
}

// ---------------- FFN up-proj (SwiGLU): 4 rows x 256-out chunk, packed ----------------
__global__ __launch_bounds__(256) void ffn1_kernel(const float* __restrict__ b1,
                                                   const float* __restrict__ b2) {
    __shared__ float4 xs[DIM];
    int i0 = blockIdx.x * 4, t = threadIdx.x;
    int o = blockIdx.y * 256 + t;
    xs[t] = make_float4(g_xn2[i0*DIM+t], g_xn2[(i0+1)*DIM+t],
                        g_xn2[(i0+2)*DIM+t], g_xn2[(i0+3)*DIM+t]);
    __syncthreads();
    if (o >= HIDN) return;
    u64 a01 = 0, a23 = 0, c01 = 0, c23 = 0;
    #pragma unroll 4
    for (int k = 0; k < DIM; k++) {
        float u = g_w1T[k*HIDN + o];
        float v = g_w2T[k*HIDN + o];
        ulonglong2 xv = *(const ulonglong2*)&xs[k];
        u64 uu = pk2(u, u), vv = pk2(v, v);
        a01 = fma2(xv.x, uu, a01); a23 = fma2(xv.y, uu, a23);
        c01 = fma2(xv.x, vv, c01); c23 = fma2(xv.y, vv, c23);
    }
    float2 A = up2(a01), B = up2(a23), C = up2(c01), D = up2(c23);
    float bb1 = b1[o], bb2 = b2[o];
    g_gate[(i0+0)*HIDN + o] = fsilu(A.x + bb1) * (C.x + bb2);
    g_gate[(i0+1)*HIDN + o] = fsilu(A.y + bb1) * (C.y + bb2);
    g_gate[(i0+2)*HIDN + o] = fsilu(B.x + bb1) * (D.x + bb2);
    g_gate[(i0+3)*HIDN + o] = fsilu(B.y + bb1) * (D.y + bb2);
}

// ---------------- FFN down-proj + residual: 2 rows, packed ----------------
__global__ __launch_bounds__(256) void ffn2_kernel(const float* __restrict__ b3,
                                                   float* __restrict__ out) {
    __shared__ float2 gs[HIDN];
    int i0 = blockIdx.x * 2, t = threadIdx.x;
    for (int idx = t; idx < HIDN; idx += 256)
        gs[idx] = make_float2(g_gate[i0*HIDN + idx], g_gate[(i0+1)*HIDN + idx]);
    __syncthreads();
    u64 acc = 0;
    #pragma unroll 2
    for (int o = 0; o < HIDN; o++) {
        float w = g_w3T[o*DIM + t];
        acc = fma2(*(const u64*)&gs[o], pk2(w, w), acc);
    }
    float2 a = up2(acc);
    float bb = b3[t];
    out[i0*DIM + t]     = g_resid[i0*DIM + t]     + a.x + bb;
    out[(i0+1)*DIM + t] = g_resid[(i0+1)*DIM + t] + a.y + bb;
}

// ---------------- launch ----------------
extern "C" void kernel_launch(void* const* d_in, const int* in_sizes, int n_in,
                              void* d_out, int out_size) {
    const float* x      = (const float*)d_in[0];
    const float* coords = (const float*)d_in[1];
    const float* ln1_w  = (const float*)d_in[2];
    const float* ln1_b  = (const float*)d_in[3];
    const float* ln2_w  = (const float*)d_in[4];
    const float* ln2_b  = (const float*)d_in[5];
    const float* qkv_w  = (const float*)d_in[6];
    const float* qkv_b  = (const float*)d_in[7];
    const float* rb1_w  = (const float*)d_in[8];
    const float* rb1_b  = (const float*)d_in[9];
    const float* rb2_w  = (const float*)d_in[10];
    const float* rb2_b  = (const float*)d_in[11];
    const float* rv1_w  = (const float*)d_in[12];
    const float* rv1_b  = (const float*)d_in[13];
    const float* rv2_w  = (const float*)d_in[14];
    const float* rv2_b  = (const float*)d_in[15];
    const float* w1     = (const float*)d_in[16];
    const float* b1     = (const float*)d_in[17];
    const float* w2     = (const float*)d_in[18];
    const float* b2     = (const float*)d_in[19];
    const float* w3     = (const float*)d_in[20];
    const float* b3     = (const float*)d_in[21];
    float* out = (float*)d_out;

    prep_kernel<<<768, 256>>>(coords, rb1_w, rv1_w, qkv_w, rv2_w, rb2_w, w1, w2, w3);
    ln_kernel<<<NTOK, 256>>>(x, ln1_w, ln1_b, 0);
    qkv_kernel<<<dim3(128, 3), 256>>>(qkv_b);
    scores_kernel<<<NTOK, 256>>>(rb1_b, rb2_b);
    attn_kernel<<<NTOK, 256>>>(x, rv1_b, rv2_b);
    ln_kernel<<<NTOK, 256>>>(x, ln2_w, ln2_b, 1);
    ffn1_kernel<<<dim3(128, 3), 256>>>(b1, b2);
    ffn2_kernel<<<256, 256>>>(b3, out);
}

// round 4
// speedup vs baseline: 1.6503x; 1.0417x over previous
#include <cuda_runtime.h>
#include <math.h>

#define NTOK 512
#define DIM 256
#define NH 8
#define HDIM 32
#define HIDN 682

typedef unsigned long long u64;

__device__ __forceinline__ u64 pk2(float lo, float hi) {
    u64 r; asm("mov.b64 %0, {%1,%2};" : "=l"(r) : "f"(lo), "f"(hi)); return r;
}
__device__ __forceinline__ float2 up2(u64 v) {
    float2 f; asm("mov.b64 {%0,%1}, %2;" : "=f"(f.x), "=f"(f.y) : "l"(v)); return f;
}
__device__ __forceinline__ u64 fma2(u64 a, u64 b, u64 c) {
    u64 d; asm("fma.rn.f32x2 %0, %1, %2, %3;" : "=l"(d) : "l"(a), "l"(b), "l"(c)); return d;
}
__device__ __forceinline__ u64 add2(u64 a, u64 b) {
    u64 d; asm("add.rn.f32x2 %0, %1, %2;" : "=l"(d) : "l"(a), "l"(b)); return d;
}
__device__ __forceinline__ float ftanh(float x) {
    float t; asm("tanh.approx.f32 %0, %1;" : "=f"(t) : "f"(x)); return t;
}
// silu(x) = h + h*tanh(h), h = x/2   (pass h directly when prescaled)
__device__ __forceinline__ float fsilu(float x) {
    float h = 0.5f * x;
    return fmaf(h, ftanh(h), h);
}

// ---------------- scratch ----------------
__device__ float g_xn[NTOK*DIM];
__device__ float g_q[NTOK*DIM];
__device__ float2 g_pbk[DIM*NTOK];    // [c][j] = {-0.5*pb, k}
__device__ float2 g_pvv[NTOK*DIM];    // [j][c] = {-0.5*pv, v}
__device__ float g_rv2T[DIM*DIM];     // [c][o]
__device__ u64   g_rb2d[DIM*NH];      // [c][h] duplicated pairs
__device__ float g_qkvT[DIM*3*DIM];   // [k][o]
__device__ float g_w1T[DIM*HIDN];     // [k][o]
__device__ float g_w2T[DIM*HIDN];
__device__ float g_w3T[HIDN*DIM];     // [o][d]
__device__ float g_scores[NTOK*NH*NTOK]; // [i][h][j]
__device__ float g_resid[NTOK*DIM];
__device__ float g_xn2[NTOK*DIM];
__device__ float g_gate[NTOK*HIDN];

// ---------------- prep: P matrices (prescaled, interleaved) + rb2 dup ----------------
__global__ void prep_p(const float* __restrict__ coords,
                       const float* __restrict__ rb1_w,
                       const float* __restrict__ rv1_w,
                       const float* __restrict__ rb2_w) {
    int idx = blockIdx.x * 256 + threadIdx.x;   // 512 blocks -> 131072
    {
        int c = idx >> 9, n = idx & 511;        // [c][n]
        float x0 = coords[n*3+0], x1 = coords[n*3+1], x2 = coords[n*3+2];
        float pb = x0*rb1_w[c*3+0] + x1*rb1_w[c*3+1] + x2*rb1_w[c*3+2];
        g_pbk[idx].x = -0.5f * pb;
    }
    {
        int n = idx >> 8, c = idx & 255;        // [n][c]
        float x0 = coords[n*3+0], x1 = coords[n*3+1], x2 = coords[n*3+2];
        float pv = x0*rv1_w[c*3+0] + x1*rv1_w[c*3+1] + x2*rv1_w[c*3+2];
        g_pvv[idx].x = -0.5f * pv;
    }
    if (idx < NH*DIM) {
        int h = idx / DIM, c = idx % DIM;
        float r = rb2_w[idx];
        g_rb2d[c*NH + h] = pk2(r, r);
    }
}

// ---------------- tiled transposes ----------------
__global__ void tr_kernel(const float* __restrict__ qkv_w,
                          const float* __restrict__ rv2_w,
                          const float* __restrict__ w1,
                          const float* __restrict__ w2,
                          const float* __restrict__ w3) {
    __shared__ float tile[32][33];
    const float* src; float* dst; int R, C;
    switch (blockIdx.z) {
        case 0: src = qkv_w; dst = g_qkvT; R = 768; C = 256; break;
        case 1: src = rv2_w; dst = g_rv2T; R = 256; C = 256; break;
        case 2: src = w1;    dst = g_w1T;  R = HIDN; C = 256; break;
        case 3: src = w2;    dst = g_w2T;  R = HIDN; C = 256; break;
        default: src = w3;   dst = g_w3T;  R = 256; C = HIDN; break;
    }
    int bx = blockIdx.x * 32, by = blockIdx.y * 32;
    if (bx >= C || by >= R) return;
    int tx = threadIdx.x, ty = threadIdx.y;
    #pragma unroll
    for (int dy = ty; dy < 32; dy += 8) {
        int r = by + dy, cc = bx + tx;
        if (r < R && cc < C) tile[dy][tx] = src[r*C + cc];
    }
    __syncthreads();
    #pragma unroll
    for (int dy = ty; dy < 32; dy += 8) {
        int r = bx + dy, cc = by + tx;   // dst is [C][R]
        if (r < C && cc < R) dst[r*R + cc] = tile[tx][dy];
    }
}

// ---------------- layernorm ----------------
__global__ void ln_kernel(const float* __restrict__ xext,
                          const float* __restrict__ w,
                          const float* __restrict__ b,
                          int mode) {
    __shared__ float sb[8];
    const float* src = (mode == 0) ? xext : g_resid;
    float* dst = (mode == 0) ? g_xn : g_xn2;
    int i = blockIdx.x, t = threadIdx.x;
    float v = src[i*DIM + t];

    float s = v;
    #pragma unroll
    for (int o = 16; o; o >>= 1) s += __shfl_xor_sync(0xffffffffu, s, o);
    if ((t & 31) == 0) sb[t >> 5] = s;
    __syncthreads();
    if (t == 0) { float a = 0.f; for (int k = 0; k < 8; k++) a += sb[k]; sb[0] = a; }
    __syncthreads();
    float mean = sb[0] * (1.0f / DIM);
    __syncthreads();

    float d = v - mean;
    float q = d * d;
    #pragma unroll
    for (int o = 16; o; o >>= 1) q += __shfl_xor_sync(0xffffffffu, q, o);
    if ((t & 31) == 0) sb[t >> 5] = q;
    __syncthreads();
    if (t == 0) { float a = 0.f; for (int k = 0; k < 8; k++) a += sb[k]; sb[0] = a; }
    __syncthreads();
    float var = sb[0] * (1.0f / DIM);
    float inv = rsqrtf(var + 1e-5f);
    dst[i*DIM + t] = d * inv * w[t] + b[t];
}

// ---------------- QKV GEMM: 4 rows, 256 outs, k-split 2, 512 threads ----------------
__global__ __launch_bounds__(512) void qkv_kernel(const float* __restrict__ qkv_b) {
    __shared__ float4 xs[DIM];
    __shared__ u64 part[256][2];
    int i0 = blockIdx.x * 4, chunk = blockIdx.y, t = threadIdx.x;
    int col = t & 255, kh = t >> 8;
    if (t < 256)
        xs[t] = make_float4(g_xn[i0*DIM+t], g_xn[(i0+1)*DIM+t],
                            g_xn[(i0+2)*DIM+t], g_xn[(i0+3)*DIM+t]);
    __syncthreads();
    int ob = chunk*256 + col;
    u64 a01 = 0, a23 = 0;
    int kbeg = kh * 128;
    #pragma unroll 4
    for (int kk = 0; kk < 128; kk++) {
        int k = kbeg + kk;
        float w = g_qkvT[k*768 + ob];
        ulonglong2 xv = *(const ulonglong2*)&xs[k];
        u64 ww = pk2(w, w);
        a01 = fma2(xv.x, ww, a01);
        a23 = fma2(xv.y, ww, a23);
    }
    if (kh == 1) { part[col][0] = a01; part[col][1] = a23; }
    __syncthreads();
    if (kh == 0) {
        a01 = add2(a01, part[col][0]);
        a23 = add2(a23, part[col][1]);
        float bb = qkv_b[ob];
        float2 A = up2(a01), B = up2(a23);
        float r[4] = { A.x+bb, A.y+bb, B.x+bb, B.y+bb };
        if (chunk == 0) {
            #pragma unroll
            for (int rr = 0; rr < 4; rr++) g_q[(i0+rr)*DIM + col] = r[rr];
        } else if (chunk == 1) {
            #pragma unroll
            for (int rr = 0; rr < 4; rr++)
                ((float*)g_pbk)[(col*NTOK + i0+rr)*2 + 1] = r[rr];
        } else {
            #pragma unroll
            for (int rr = 0; rr < 4; rr++)
                ((float*)g_pvv)[((i0+rr)*DIM + col)*2 + 1] = r[rr];
        }
    }
}

// ---------------- scores: 2 i x 256 j per block, i-packed bias ----------------
__global__ __launch_bounds__(256) void scores_kernel(const float* __restrict__ rb1_b,
                                                     const float* __restrict__ rb2_b) {
    __shared__ u64 pbq[DIM][2];     // [c] = { (pbh_i0, pbh_i1), (q_i0, q_i1) }
    __shared__ u64 rbs[DIM*NH];     // 16KB duplicated rb2
    int i0 = (blockIdx.x >> 1) * 2;
    int t = threadIdx.x;
    int j = (blockIdx.x & 1) * 256 + t;

    {
        float bh = 0.5f * rb1_b[t];
        float p0 = bh - g_pbk[t*NTOK + i0].x;      // = 0.5*pb_i0 + 0.5*b
        float p1 = bh - g_pbk[t*NTOK + i0 + 1].x;
        pbq[t][0] = pk2(p0, p1);
        pbq[t][1] = pk2(g_q[i0*DIM + t], g_q[(i0+1)*DIM + t]);
    }
    #pragma unroll
    for (int m = 0; m < 8; m++) rbs[m*256 + t] = g_rb2d[m*256 + t];
    __syncthreads();

    u64 accb[8] = {}, accs[8] = {};
    #pragma unroll
    for (int h = 0; h < NH; h++) {
        #pragma unroll 4
        for (int c32 = 0; c32 < 32; c32++) {
            int c = h*32 + c32;
            float2 pkv = g_pbk[c*NTOK + j];          // {-0.5pb_j, k_j}
            u64 pbn = pk2(pkv.x, pkv.x);
            u64 kd  = pk2(pkv.y, pkv.y);
            ulonglong2 pq = *(const ulonglong2*)&pbq[c][0];
            u64 h2 = add2(pq.x, pbn);                // packed silu half-arg over i
            float2 sh = up2(h2);
            u64 t2 = pk2(ftanh(sh.x), ftanh(sh.y));
            u64 hb2 = fma2(h2, t2, h2);              // silu values, packed over i
            ulonglong2 rA = *(const ulonglong2*)&rbs[c*8 + 0];
            ulonglong2 rB = *(const ulonglong2*)&rbs[c*8 + 2];
            ulonglong2 rC = *(const ulonglong2*)&rbs[c*8 + 4];
            ulonglong2 rD = *(const ulonglong2*)&rbs[c*8 + 6];
            accb[0] = fma2(hb2, rA.x, accb[0]); accb[1] = fma2(hb2, rA.y, accb[1]);
            accb[2] = fma2(hb2, rB.x, accb[2]); accb[3] = fma2(hb2, rB.y, accb[3]);
            accb[4] = fma2(hb2, rC.x, accb[4]); accb[5] = fma2(hb2, rC.y, accb[5]);
            accb[6] = fma2(hb2, rD.x, accb[6]); accb[7] = fma2(hb2, rD.y, accb[7]);
            accs[h] = fma2(pq.y, kd, accs[h]);
        }
    }
    const float sc = 0.17677669529663687f;
    #pragma unroll
    for (int h = 0; h < NH; h++) {
        float2 b = up2(accb[h]);
        float2 qk = up2(accs[h]);
        float rbb = rb2_b[h];
        g_scores[(i0*NH + h)*NTOK + j]     = fmaf(qk.x, sc, b.x + rbb);
        g_scores[((i0+1)*NH + h)*NTOK + j] = fmaf(qk.y, sc, b.y + rbb);
    }
}

// ---------------- attention ----------------
__global__ __launch_bounds__(256, 4) void attn_kernel(const float* __restrict__ x,
                                                      const float* __restrict__ rv1_b,
                                                      const float* __restrict__ rv2_b) {
    __shared__ float wT[NTOK*12];     // wT[j][h], padded
    __shared__ float whid[NH*DIM];
    __shared__ float sinv[NH];
    int i = blockIdx.x, t = threadIdx.x;
    int wid = t >> 5, lane = t & 31;

    { // unnormalized softmax for head h = wid, stored transposed
        const float* row = g_scores + (i*NH + wid)*NTOK;
        float m = -1e30f;
        for (int jj = lane; jj < NTOK; jj += 32) m = fmaxf(m, row[jj]);
        #pragma unroll
        for (int o = 16; o; o >>= 1) m = fmaxf(m, __shfl_xor_sync(0xffffffffu, m, o));
        float s = 0.f;
        for (int jj = lane; jj < NTOK; jj += 32) {
            float e = __expf(row[jj] - m);
            wT[jj*12 + wid] = e;
            s += e;
        }
        #pragma unroll
        for (int o = 16; o; o >>= 1) s += __shfl_xor_sync(0xffffffffu, s, o);
        if (lane == 0) sinv[wid] = __fdividef(1.0f, s);
    }
    __syncthreads();

    float pvih = 0.5f*rv1_b[t] - g_pvv[i*DIM + t].x;   // 0.5*pv_i + 0.5*b
    int hs = t >> 5;
    u64 accW[4] = {};
    float accC = 0.f;
    #pragma unroll 2
    for (int j = 0; j < NTOK; j++) {
        float2 pv = g_pvv[j*DIM + t];                   // {-0.5pv_j, v_j}
        ulonglong2 wA = *(const ulonglong2*)&wT[j*12];
        ulonglong2 wB = *(const ulonglong2*)&wT[j*12 + 4];
        float hin = pvih + pv.x;
        float hv = fmaf(hin, ftanh(hin), hin);
        u64 hh = pk2(hv, hv);
        accW[0] = fma2(hh, wA.x, accW[0]); accW[1] = fma2(hh, wA.y, accW[1]);
        accW[2] = fma2(hh, wB.x, accW[2]); accW[3] = fma2(hh, wB.y, accW[3]);
        accC += wT[j*12 + hs] * pv.y;  // warp-uniform LDS broadcast
    }
    #pragma unroll
    for (int hp = 0; hp < 4; hp++) {
        float2 v = up2(accW[hp]);
        whid[(2*hp)*DIM + t]   = v.x * sinv[2*hp];
        whid[(2*hp+1)*DIM + t] = v.y * sinv[2*hp+1];
    }
    accC *= sinv[hs];
    __syncthreads();

    float accP = 0.f;
    #pragma unroll 4
    for (int c = 0; c < DIM; c++)
        accP += whid[hs*DIM + c] * g_rv2T[c*DIM + t];

    g_resid[i*DIM + t] = x[i*DIM + t] + accC + accP + rv2_b[t];
}

// ---------------- FFN up-proj (SwiGLU): 4 rows, k-split 2, 512 threads ----------------
__global__ __launch_bounds__(512) void ffn1_kernel(const float* __restrict__ b1,
                                                   const float* __restrict__ b2) {
    __shared__ float4 xs[DIM];
    __shared__ u64 parta[256][2];
    __shared__ u64 partc[256][2];
    int i0 = blockIdx.x * 4, t = threadIdx.x;
    int col = t & 255, kh = t >> 8;
    int o = blockIdx.y*256 + col;
    int ocl = (o < HIDN) ? o : 0;
    if (t < 256)
        xs[t] = make_float4(g_xn2[i0*DIM+t], g_xn2[(i0+1)*DIM+t],
                            g_xn2[(i0+2)*DIM+t], g_xn2[(i0+3)*DIM+t]);
    __syncthreads();
    u64 a01 = 0, a23 = 0, c01 = 0, c23 = 0;
    int kbeg = kh * 128;
    #pragma unroll 4
    for (int kk = 0; kk < 128; kk++) {
        int k = kbeg + kk;
        float u = g_w1T[k*HIDN + ocl];
        float v = g_w2T[k*HIDN + ocl];
        ulonglong2 xv = *(const ulonglong2*)&xs[k];
        u64 uu = pk2(u, u), vv = pk2(v, v);
        a01 = fma2(xv.x, uu, a01); a23 = fma2(xv.y, uu, a23);
        c01 = fma2(xv.x, vv, c01); c23 = fma2(xv.y, vv, c23);
    }
    if (kh == 1) {
        parta[col][0] = a01; parta[col][1] = a23;
        partc[col][0] = c01; partc[col][1] = c23;
    }
    __syncthreads();
    if (kh == 0 && o < HIDN) {
        a01 = add2(a01, parta[col][0]); a23 = add2(a23, parta[col][1]);
        c01 = add2(c01, partc[col][0]); c23 = add2(c23, partc[col][1]);
        float2 A = up2(a01), B = up2(a23), C = up2(c01), D = up2(c23);
        float bb1 = b1[o], bb2 = b2[o];
        g_gate[(i0+0)*HIDN + o] = fsilu(A.x + bb1) * (C.x + bb2);
        g_gate[(i0+1)*HIDN + o] = fsilu(A.y + bb1) * (C.y + bb2);
        g_gate[(i0+2)*HIDN + o] = fsilu(B.x + bb1) * (D.x + bb2);
        g_gate[(i0+3)*HIDN + o] = fsilu(B.y + bb1) * (D.y + bb2);
    }
}

// ---------------- FFN down-proj + residual: 2 rows, k-split 2, 512 threads ----------------
__global__ __launch_bounds__(512) void ffn2_kernel(const float* __restrict__ b3,
                                                   float* __restrict__ out) {
    __shared__ float2 gs[HIDN];
    __shared__ u64 part[256];
    int i0 = blockIdx.x * 2, t = threadIdx.x;
    int col = t & 255, half = t >> 8;
    for (int idx = t; idx < HIDN; idx += 512)
        gs[idx] = make_float2(g_gate[i0*HIDN + idx], g_gate[(i0+1)*HIDN + idx]);
    __syncthreads();
    u64 acc = 0;
    int ob = half * 341;
    #pragma unroll 2
    for (int m = 0; m < 341; m++) {
        int o = ob + m;
        float w = g_w3T[o*DIM + col];
        acc = fma2(*(const u64*)&gs[o], pk2(w, w), acc);
    }
    if (half == 1) part[col] = acc;
    __syncthreads();
    if (half == 0) {
        acc = add2(acc, part[col]);
        float2 a = up2(acc);
        float bb = b3[col];
        out[i0*DIM + col]     = g_resid[i0*DIM + col]     + a.x + bb;
        out[(i0+1)*DIM + col] = g_resid[(i0+1)*DIM + col] + a.y + bb;
    }
}

// ---------------- launch ----------------
extern "C" void kernel_launch(void* const* d_in, const int* in_sizes, int n_in,
                              void* d_out, int out_size) {
    const float* x      = (const float*)d_in[0];
    const float* coords = (const float*)d_in[1];
    const float* ln1_w  = (const float*)d_in[2];
    const float* ln1_b  = (const float*)d_in[3];
    const float* ln2_w  = (const float*)d_in[4];
    const float* ln2_b  = (const float*)d_in[5];
    const float* qkv_w  = (const float*)d_in[6];
    const float* qkv_b  = (const float*)d_in[7];
    const float* rb1_w  = (const float*)d_in[8];
    const float* rb1_b  = (const float*)d_in[9];
    const float* rb2_w  = (const float*)d_in[10];
    const float* rb2_b  = (const float*)d_in[11];
    const float* rv1_w  = (const float*)d_in[12];
    const float* rv1_b  = (const float*)d_in[13];
    const float* rv2_w  = (const float*)d_in[14];
    const float* rv2_b  = (const float*)d_in[15];
    const float* w1     = (const float*)d_in[16];
    const float* b1     = (const float*)d_in[17];
    const float* w2     = (const float*)d_in[18];
    const float* b2     = (const float*)d_in[19];
    const float* w3     = (const float*)d_in[20];
    const float* b3     = (const float*)d_in[21];
    float* out = (float*)d_out;

    prep_p<<<512, 256>>>(coords, rb1_w, rv1_w, rb2_w);
    tr_kernel<<<dim3(22, 24, 5), dim3(32, 8)>>>(qkv_w, rv2_w, w1, w2, w3);
    ln_kernel<<<NTOK, 256>>>(x, ln1_w, ln1_b, 0);
    qkv_kernel<<<dim3(128, 3), 512>>>(qkv_b);
    scores_kernel<<<NTOK, 256>>>(rb1_b, rb2_b);
    attn_kernel<<<NTOK, 256>>>(x, rv1_b, rv2_b);
    ln_kernel<<<NTOK, 256>>>(x, ln2_w, ln2_b, 1);
    ffn1_kernel<<<dim3(128, 3), 512>>>(b1, b2);
    ffn2_kernel<<<256, 512>>>(b3, out);
}

// round 5
// speedup vs baseline: 2.1059x; 1.2761x over previous
#include <cuda_runtime.h>
#include <math.h>

#define NTOK 512
#define DIM 256
#define NH 8
#define HDIM 32
#define HIDN 682

typedef unsigned long long u64;

__device__ __forceinline__ u64 pk2(float lo, float hi) {
    u64 r; asm("mov.b64 %0, {%1,%2};" : "=l"(r) : "f"(lo), "f"(hi)); return r;
}
__device__ __forceinline__ float2 up2(u64 v) {
    float2 f; asm("mov.b64 {%0,%1}, %2;" : "=f"(f.x), "=f"(f.y) : "l"(v)); return f;
}
__device__ __forceinline__ u64 fma2(u64 a, u64 b, u64 c) {
    u64 d; asm("fma.rn.f32x2 %0, %1, %2, %3;" : "=l"(d) : "l"(a), "l"(b), "l"(c)); return d;
}
__device__ __forceinline__ u64 add2(u64 a, u64 b) {
    u64 d; asm("add.rn.f32x2 %0, %1, %2;" : "=l"(d) : "l"(a), "l"(b)); return d;
}
__device__ __forceinline__ float ftanh(float x) {
    float t; asm("tanh.approx.f32 %0, %1;" : "=f"(t) : "f"(x)); return t;
}
__device__ __forceinline__ float fsilu(float x) {
    float h = 0.5f * x;
    return fmaf(h, ftanh(h), h);
}

// ---------------- scratch ----------------
__device__ float g_q[NTOK*DIM];
__device__ float2 g_pbk[DIM*NTOK];    // [c][j] = {-0.5*pb, k}
__device__ float2 g_pvv[NTOK*DIM];    // [j][c] = {-0.5*pv, v}
__device__ float g_rv2T[DIM*DIM];     // [c][o]
__device__ u64   g_rb2d[DIM*NH];      // [c][h] duplicated pairs
__device__ float g_qkvT[DIM*3*DIM];   // [k][o]
__device__ float g_w1T[DIM*HIDN];     // [k][o]
__device__ float g_w2T[DIM*HIDN];
__device__ float g_w3T[HIDN*DIM];     // [o][d]
__device__ float g_scores[NTOK*NH*NTOK]; // [i][h][j]
__device__ float g_resid[NTOK*DIM];
__device__ float g_gate[NTOK*HIDN];

// ---------------- prep: P matrices (prescaled, interleaved) + rb2 dup ----------------
__global__ void prep_p(const float* __restrict__ coords,
                       const float* __restrict__ rb1_w,
                       const float* __restrict__ rv1_w,
                       const float* __restrict__ rb2_w) {
    int idx = blockIdx.x * 256 + threadIdx.x;   // 512 blocks -> 131072
    {
        int c = idx >> 9, n = idx & 511;        // [c][n]
        float x0 = coords[n*3+0], x1 = coords[n*3+1], x2 = coords[n*3+2];
        float pb = x0*rb1_w[c*3+0] + x1*rb1_w[c*3+1] + x2*rb1_w[c*3+2];
        g_pbk[idx].x = -0.5f * pb;
    }
    {
        int n = idx >> 8, c = idx & 255;        // [n][c]
        float x0 = coords[n*3+0], x1 = coords[n*3+1], x2 = coords[n*3+2];
        float pv = x0*rv1_w[c*3+0] + x1*rv1_w[c*3+1] + x2*rv1_w[c*3+2];
        g_pvv[idx].x = -0.5f * pv;
    }
    if (idx < NH*DIM) {
        int h = idx / DIM, c = idx % DIM;
        float r = rb2_w[idx];
        g_rb2d[c*NH + h] = pk2(r, r);
    }
}

// ---------------- tiled transposes ----------------
__global__ void tr_kernel(const float* __restrict__ qkv_w,
                          const float* __restrict__ rv2_w,
                          const float* __restrict__ w1,
                          const float* __restrict__ w2,
                          const float* __restrict__ w3) {
    __shared__ float tile[32][33];
    const float* src; float* dst; int R, C;
    switch (blockIdx.z) {
        case 0: src = qkv_w; dst = g_qkvT; R = 768; C = 256; break;
        case 1: src = rv2_w; dst = g_rv2T; R = 256; C = 256; break;
        case 2: src = w1;    dst = g_w1T;  R = HIDN; C = 256; break;
        case 3: src = w2;    dst = g_w2T;  R = HIDN; C = 256; break;
        default: src = w3;   dst = g_w3T;  R = 256; C = HIDN; break;
    }
    int bx = blockIdx.x * 32, by = blockIdx.y * 32;
    if (bx >= C || by >= R) return;
    int tx = threadIdx.x, ty = threadIdx.y;
    #pragma unroll
    for (int dy = ty; dy < 32; dy += 8) {
        int r = by + dy, cc = bx + tx;
        if (r < R && cc < C) tile[dy][tx] = src[r*C + cc];
    }
    __syncthreads();
    #pragma unroll
    for (int dy = ty; dy < 32; dy += 8) {
        int r = bx + dy, cc = by + tx;   // dst is [C][R]
        if (r < C && cc < R) dst[r*R + cc] = tile[tx][dy];
    }
}

// ---- in-block LayerNorm of 4 rows into xs[c] (float4 over rows) ----
// t: 512 threads; row r = t>>7, col pair cc = (t&127)*2
__device__ __forceinline__ void block_ln4(const float* __restrict__ src, int i0,
                                          const float* __restrict__ lnw,
                                          const float* __restrict__ lnb,
                                          float4* xs, float2 (*red2)[4]) {
    int t = threadIdx.x;
    int lane = t & 31, r = t >> 7, wir = (t >> 5) & 3;
    int cc = (t & 127) * 2;
    float2 xv = *(const float2*)&src[(i0+r)*DIM + cc];
    float s1 = xv.x + xv.y;
    float s2 = fmaf(xv.x, xv.x, xv.y*xv.y);
    #pragma unroll
    for (int o = 16; o; o >>= 1) {
        s1 += __shfl_xor_sync(0xffffffffu, s1, o);
        s2 += __shfl_xor_sync(0xffffffffu, s2, o);
    }
    if (lane == 0) red2[r][wir] = make_float2(s1, s2);
    __syncthreads();
    float S1 = red2[r][0].x + red2[r][1].x + red2[r][2].x + red2[r][3].x;
    float S2 = red2[r][0].y + red2[r][1].y + red2[r][2].y + red2[r][3].y;
    float mean = S1 * (1.0f/256.0f);
    float var  = S2 * (1.0f/256.0f) - mean*mean;
    float inv  = rsqrtf(var + 1e-5f);
    float2 wv = *(const float2*)&lnw[cc];
    float2 bv = *(const float2*)&lnb[cc];
    ((float*)&xs[cc])[r]   = (xv.x - mean)*inv*wv.x + bv.x;
    ((float*)&xs[cc+1])[r] = (xv.y - mean)*inv*wv.y + bv.y;
    __syncthreads();
}

// ---------------- QKV (LN1 fused): 4 rows, 256-col chunk, 2 cols/thread, k-split 4 ----------------
__global__ __launch_bounds__(512) void qkv_kernel(const float* __restrict__ x,
                                                  const float* __restrict__ ln1_w,
                                                  const float* __restrict__ ln1_b,
                                                  const float* __restrict__ qkv_b) {
    __shared__ float4 xs[DIM];
    __shared__ float2 red2[4][4];
    __shared__ u64 part[128][3][4];
    int t = threadIdx.x;
    int i0 = blockIdx.x * 4, chunk = blockIdx.y;
    block_ln4(x, i0, ln1_w, ln1_b, xs, red2);

    int p = t & 127, kh = t >> 7;
    int ob = chunk*256 + p*2;
    u64 a0 = 0, a1 = 0, b0 = 0, b1 = 0;   // (col0 r01,r23), (col1 r01,r23)
    int kbeg = kh * 64;
    #pragma unroll 4
    for (int kk = 0; kk < 64; kk++) {
        int k = kbeg + kk;
        float2 w2 = *(const float2*)&g_qkvT[k*768 + ob];
        ulonglong2 xv = *(const ulonglong2*)&xs[k];
        u64 w0 = pk2(w2.x, w2.x), w1 = pk2(w2.y, w2.y);
        a0 = fma2(xv.x, w0, a0); a1 = fma2(xv.y, w0, a1);
        b0 = fma2(xv.x, w1, b0); b1 = fma2(xv.y, w1, b1);
    }
    if (kh) { part[p][kh-1][0]=a0; part[p][kh-1][1]=a1; part[p][kh-1][2]=b0; part[p][kh-1][3]=b1; }
    __syncthreads();
    if (kh == 0) {
        #pragma unroll
        for (int m = 0; m < 3; m++) {
            a0 = add2(a0, part[p][m][0]); a1 = add2(a1, part[p][m][1]);
            b0 = add2(b0, part[p][m][2]); b1 = add2(b1, part[p][m][3]);
        }
        float2 bb = *(const float2*)&qkv_b[ob];
        float2 A = up2(a0), B = up2(a1), C = up2(b0), D = up2(b1);
        float r0[4] = { A.x+bb.x, A.y+bb.x, B.x+bb.x, B.y+bb.x };  // col ob, rows 0..3
        float r1[4] = { C.x+bb.y, C.y+bb.y, D.x+bb.y, D.y+bb.y };  // col ob+1
        if (chunk == 0) {
            #pragma unroll
            for (int rr = 0; rr < 4; rr++) {
                g_q[(i0+rr)*DIM + ob]   = r0[rr];
                g_q[(i0+rr)*DIM + ob+1] = r1[rr];
            }
        } else if (chunk == 1) {
            int c0 = ob - 256;
            #pragma unroll
            for (int rr = 0; rr < 4; rr++) {
                ((float*)g_pbk)[(c0*NTOK + i0+rr)*2 + 1]     = r0[rr];
                ((float*)g_pbk)[((c0+1)*NTOK + i0+rr)*2 + 1] = r1[rr];
            }
        } else {
            int c0 = ob - 512;
            #pragma unroll
            for (int rr = 0; rr < 4; rr++) {
                ((float*)g_pvv)[((i0+rr)*DIM + c0)*2 + 1]   = r0[rr];
                ((float*)g_pvv)[((i0+rr)*DIM + c0+1)*2 + 1] = r1[rr];
            }
        }
    }
}

// ---------------- scores: 2 i x 256 j per block, i-packed bias ----------------
__global__ __launch_bounds__(256) void scores_kernel(const float* __restrict__ rb1_b,
                                                     const float* __restrict__ rb2_b) {
    __shared__ u64 pbq[DIM][2];
    __shared__ u64 rbs[DIM*NH];
    int i0 = (blockIdx.x >> 1) * 2;
    int t = threadIdx.x;
    int j = (blockIdx.x & 1) * 256 + t;

    {
        float bh = 0.5f * rb1_b[t];
        float p0 = bh - g_pbk[t*NTOK + i0].x;
        float p1 = bh - g_pbk[t*NTOK + i0 + 1].x;
        pbq[t][0] = pk2(p0, p1);
        pbq[t][1] = pk2(g_q[i0*DIM + t], g_q[(i0+1)*DIM + t]);
    }
    #pragma unroll
    for (int m = 0; m < 8; m++) rbs[m*256 + t] = g_rb2d[m*256 + t];
    __syncthreads();

    u64 accb[8] = {}, accs[8] = {};
    #pragma unroll
    for (int h = 0; h < NH; h++) {
        #pragma unroll 4
        for (int c32 = 0; c32 < 32; c32++) {
            int c = h*32 + c32;
            float2 pkv = g_pbk[c*NTOK + j];
            u64 pbn = pk2(pkv.x, pkv.x);
            u64 kd  = pk2(pkv.y, pkv.y);
            ulonglong2 pq = *(const ulonglong2*)&pbq[c][0];
            u64 h2 = add2(pq.x, pbn);
            float2 sh = up2(h2);
            u64 t2 = pk2(ftanh(sh.x), ftanh(sh.y));
            u64 hb2 = fma2(h2, t2, h2);
            ulonglong2 rA = *(const ulonglong2*)&rbs[c*8 + 0];
            ulonglong2 rB = *(const ulonglong2*)&rbs[c*8 + 2];
            ulonglong2 rC = *(const ulonglong2*)&rbs[c*8 + 4];
            ulonglong2 rD = *(const ulonglong2*)&rbs[c*8 + 6];
            accb[0] = fma2(hb2, rA.x, accb[0]); accb[1] = fma2(hb2, rA.y, accb[1]);
            accb[2] = fma2(hb2, rB.x, accb[2]); accb[3] = fma2(hb2, rB.y, accb[3]);
            accb[4] = fma2(hb2, rC.x, accb[4]); accb[5] = fma2(hb2, rC.y, accb[5]);
            accb[6] = fma2(hb2, rD.x, accb[6]); accb[7] = fma2(hb2, rD.y, accb[7]);
            accs[h] = fma2(pq.y, kd, accs[h]);
        }
    }
    const float sc = 0.17677669529663687f;
    #pragma unroll
    for (int h = 0; h < NH; h++) {
        float2 b = up2(accb[h]);
        float2 qk = up2(accs[h]);
        float rbb = rb2_b[h];
        g_scores[(i0*NH + h)*NTOK + j]     = fmaf(qk.x, sc, b.x + rbb);
        g_scores[((i0+1)*NH + h)*NTOK + j] = fmaf(qk.y, sc, b.y + rbb);
    }
}

// ---------------- attention ----------------
__global__ __launch_bounds__(256, 4) void attn_kernel(const float* __restrict__ x,
                                                      const float* __restrict__ rv1_b,
                                                      const float* __restrict__ rv2_b) {
    __shared__ float wT[NTOK*12];
    __shared__ float whid[NH*DIM];
    __shared__ float sinv[NH];
    int i = blockIdx.x, t = threadIdx.x;
    int wid = t >> 5, lane = t & 31;

    {
        const float* row = g_scores + (i*NH + wid)*NTOK;
        float m = -1e30f;
        for (int jj = lane; jj < NTOK; jj += 32) m = fmaxf(m, row[jj]);
        #pragma unroll
        for (int o = 16; o; o >>= 1) m = fmaxf(m, __shfl_xor_sync(0xffffffffu, m, o));
        float s = 0.f;
        for (int jj = lane; jj < NTOK; jj += 32) {
            float e = __expf(row[jj] - m);
            wT[jj*12 + wid] = e;
            s += e;
        }
        #pragma unroll
        for (int o = 16; o; o >>= 1) s += __shfl_xor_sync(0xffffffffu, s, o);
        if (lane == 0) sinv[wid] = __fdividef(1.0f, s);
    }
    __syncthreads();

    float pvih = 0.5f*rv1_b[t] - g_pvv[i*DIM + t].x;
    int hs = t >> 5;
    u64 accW[4] = {};
    float accC = 0.f;
    #pragma unroll 2
    for (int j = 0; j < NTOK; j++) {
        float2 pv = g_pvv[j*DIM + t];
        ulonglong2 wA = *(const ulonglong2*)&wT[j*12];
        ulonglong2 wB = *(const ulonglong2*)&wT[j*12 + 4];
        float hin = pvih + pv.x;
        float hv = fmaf(hin, ftanh(hin), hin);
        u64 hh = pk2(hv, hv);
        accW[0] = fma2(hh, wA.x, accW[0]); accW[1] = fma2(hh, wA.y, accW[1]);
        accW[2] = fma2(hh, wB.x, accW[2]); accW[3] = fma2(hh, wB.y, accW[3]);
        accC += wT[j*12 + hs] * pv.y;
    }
    #pragma unroll
    for (int hp = 0; hp < 4; hp++) {
        float2 v = up2(accW[hp]);
        whid[(2*hp)*DIM + t]   = v.x * sinv[2*hp];
        whid[(2*hp+1)*DIM + t] = v.y * sinv[2*hp+1];
    }
    accC *= sinv[hs];
    __syncthreads();

    float accP = 0.f;
    #pragma unroll 4
    for (int c = 0; c < DIM; c++)
        accP += whid[hs*DIM + c] * g_rv2T[c*DIM + t];

    g_resid[i*DIM + t] = x[i*DIM + t] + accC + accP + rv2_b[t];
}

// ---------------- FFN up (LN2 fused): 4 rows, 2 cols/thread, k-split 4 ----------------
__global__ __launch_bounds__(512) void ffn1_kernel(const float* __restrict__ ln2_w,
                                                   const float* __restrict__ ln2_b,
                                                   const float* __restrict__ b1,
                                                   const float* __restrict__ b2) {
    __shared__ float4 xs[DIM];
    __shared__ float2 red2[4][4];
    __shared__ u64 parta[128][3][4];
    __shared__ u64 partc[128][3][4];
    int t = threadIdx.x;
    int i0 = blockIdx.x * 4, chunk = blockIdx.y;
    block_ln4(g_resid, i0, ln2_w, ln2_b, xs, red2);

    int p = t & 127, kh = t >> 7;
    int o = chunk*256 + p*2;
    int ocl = (o <= HIDN-2) ? o : (HIDN-2);
    u64 a0=0, a1=0, a2=0, a3=0, c0=0, c1=0, c2=0, c3=0;
    int kbeg = kh * 64;
    #pragma unroll 4
    for (int kk = 0; kk < 64; kk++) {
        int k = kbeg + kk;
        float2 u2 = *(const float2*)&g_w1T[k*HIDN + ocl];
        float2 v2 = *(const float2*)&g_w2T[k*HIDN + ocl];
        ulonglong2 xv = *(const ulonglong2*)&xs[k];
        u64 u0 = pk2(u2.x,u2.x), u1 = pk2(u2.y,u2.y);
        u64 v0 = pk2(v2.x,v2.x), v1 = pk2(v2.y,v2.y);
        a0 = fma2(xv.x,u0,a0); a1 = fma2(xv.y,u0,a1);
        a2 = fma2(xv.x,u1,a2); a3 = fma2(xv.y,u1,a3);
        c0 = fma2(xv.x,v0,c0); c1 = fma2(xv.y,v0,c1);
        c2 = fma2(xv.x,v1,c2); c3 = fma2(xv.y,v1,c3);
    }
    if (kh) {
        parta[p][kh-1][0]=a0; parta[p][kh-1][1]=a1; parta[p][kh-1][2]=a2; parta[p][kh-1][3]=a3;
        partc[p][kh-1][0]=c0; partc[p][kh-1][1]=c1; partc[p][kh-1][2]=c2; partc[p][kh-1][3]=c3;
    }
    __syncthreads();
    if (kh == 0 && o < HIDN) {
        #pragma unroll
        for (int m = 0; m < 3; m++) {
            a0 = add2(a0, parta[p][m][0]); a1 = add2(a1, parta[p][m][1]);
            a2 = add2(a2, parta[p][m][2]); a3 = add2(a3, parta[p][m][3]);
            c0 = add2(c0, partc[p][m][0]); c1 = add2(c1, partc[p][m][1]);
            c2 = add2(c2, partc[p][m][2]); c3 = add2(c3, partc[p][m][3]);
        }
        float2 A0 = up2(a0), A1 = up2(a1), A2 = up2(a2), A3 = up2(a3);
        float2 C0 = up2(c0), C1 = up2(c1), C2 = up2(c2), C3 = up2(c3);
        float bb10 = b1[o], bb11 = b1[o+1], bb20 = b2[o], bb21 = b2[o+1];
        g_gate[(i0+0)*HIDN + o]   = fsilu(A0.x + bb10) * (C0.x + bb20);
        g_gate[(i0+1)*HIDN + o]   = fsilu(A0.y + bb10) * (C0.y + bb20);
        g_gate[(i0+2)*HIDN + o]   = fsilu(A1.x + bb10) * (C1.x + bb20);
        g_gate[(i0+3)*HIDN + o]   = fsilu(A1.y + bb10) * (C1.y + bb20);
        g_gate[(i0+0)*HIDN + o+1] = fsilu(A2.x + bb11) * (C2.x + bb21);
        g_gate[(i0+1)*HIDN + o+1] = fsilu(A2.y + bb11) * (C2.y + bb21);
        g_gate[(i0+2)*HIDN + o+1] = fsilu(A3.x + bb11) * (C3.x + bb21);
        g_gate[(i0+3)*HIDN + o+1] = fsilu(A3.y + bb11) * (C3.y + bb21);
    }
}

// ---------------- FFN down + residual: 2 rows, 2 cols/thread, o-split 4 ----------------
__global__ __launch_bounds__(512) void ffn2_kernel(const float* __restrict__ b3,
                                                   float* __restrict__ out) {
    __shared__ float2 gs[HIDN];
    __shared__ u64 part[128][3][2];
    int i0 = blockIdx.x * 2, t = threadIdx.x;
    int p = t & 127, oh = t >> 7;
    for (int idx = t; idx < HIDN; idx += 512)
        gs[idx] = make_float2(g_gate[i0*HIDN + idx], g_gate[(i0+1)*HIDN + idx]);
    __syncthreads();
    const int obeg[5] = {0, 171, 342, 512, 682};
    int os = obeg[oh], oe = obeg[oh+1];
    int d = p*2;
    u64 acc0 = 0, acc1 = 0;   // cols d, d+1 (rows packed)
    for (int o = os; o < oe; o++) {
        float2 w = *(const float2*)&g_w3T[o*DIM + d];
        u64 g2 = *(const u64*)&gs[o];
        acc0 = fma2(g2, pk2(w.x, w.x), acc0);
        acc1 = fma2(g2, pk2(w.y, w.y), acc1);
    }
    if (oh) { part[p][oh-1][0] = acc0; part[p][oh-1][1] = acc1; }
    __syncthreads();
    if (oh == 0) {
        #pragma unroll
        for (int m = 0; m < 3; m++) {
            acc0 = add2(acc0, part[p][m][0]);
            acc1 = add2(acc1, part[p][m][1]);
        }
        float2 A = up2(acc0), B = up2(acc1);
        float2 bb = *(const float2*)&b3[d];
        out[i0*DIM + d]       = g_resid[i0*DIM + d]       + A.x + bb.x;
        out[(i0+1)*DIM + d]   = g_resid[(i0+1)*DIM + d]   + A.y + bb.x;
        out[i0*DIM + d+1]     = g_resid[i0*DIM + d+1]     + B.x + bb.y;
        out[(i0+1)*DIM + d+1] = g_resid[(i0+1)*DIM + d+1] + B.y + bb.y;
    }
}

// ---------------- launch ----------------
extern "C" void kernel_launch(void* const* d_in, const int* in_sizes, int n_in,
                              void* d_out, int out_size) {
    const float* x      = (const float*)d_in[0];
    const float* coords = (const float*)d_in[1];
    const float* ln1_w  = (const float*)d_in[2];
    const float* ln1_b  = (const float*)d_in[3];
    const float* ln2_w  = (const float*)d_in[4];
    const float* ln2_b  = (const float*)d_in[5];
    const float* qkv_w  = (const float*)d_in[6];
    const float* qkv_b  = (const float*)d_in[7];
    const float* rb1_w  = (const float*)d_in[8];
    const float* rb1_b  = (const float*)d_in[9];
    const float* rb2_w  = (const float*)d_in[10];
    const float* rb2_b  = (const float*)d_in[11];
    const float* rv1_w  = (const float*)d_in[12];
    const float* rv1_b  = (const float*)d_in[13];
    const float* rv2_w  = (const float*)d_in[14];
    const float* rv2_b  = (const float*)d_in[15];
    const float* w1     = (const float*)d_in[16];
    const float* b1     = (const float*)d_in[17];
    const float* w2     = (const float*)d_in[18];
    const float* b2     = (const float*)d_in[19];
    const float* w3     = (const float*)d_in[20];
    const float* b3     = (const float*)d_in[21];
    float* out = (float*)d_out;

    prep_p<<<512, 256>>>(coords, rb1_w, rv1_w, rb2_w);
    tr_kernel<<<dim3(22, 24, 5), dim3(32, 8)>>>(qkv_w, rv2_w, w1, w2, w3);
    qkv_kernel<<<dim3(128, 3), 512>>>(x, ln1_w, ln1_b, qkv_b);
    scores_kernel<<<NTOK, 256>>>(rb1_b, rb2_b);
    attn_kernel<<<NTOK, 256>>>(x, rv1_b, rv2_b);
    ffn1_kernel<<<dim3(128, 3), 512>>>(ln2_w, ln2_b, b1, b2);
    ffn2_kernel<<<256, 512>>>(b3, out);
}

// round 7
// speedup vs baseline: 2.3560x; 1.1188x over previous
#include <cuda_runtime.h>
#include <math.h>

#define NTOK 512
#define DIM 256
#define NH 8
#define HDIM 32
#define HIDN 682

typedef unsigned long long u64;

__device__ __forceinline__ u64 pk2(float lo, float hi) {
    u64 r; asm("mov.b64 %0, {%1,%2};" : "=l"(r) : "f"(lo), "f"(hi)); return r;
}
__device__ __forceinline__ float2 up2(u64 v) {
    float2 f; asm("mov.b64 {%0,%1}, %2;" : "=f"(f.x), "=f"(f.y) : "l"(v)); return f;
}
__device__ __forceinline__ u64 fma2(u64 a, u64 b, u64 c) {
    u64 d; asm("fma.rn.f32x2 %0, %1, %2, %3;" : "=l"(d) : "l"(a), "l"(b), "l"(c)); return d;
}
__device__ __forceinline__ u64 add2(u64 a, u64 b) {
    u64 d; asm("add.rn.f32x2 %0, %1, %2;" : "=l"(d) : "l"(a), "l"(b)); return d;
}
__device__ __forceinline__ float ftanh(float x) {
    float t; asm("tanh.approx.f32 %0, %1;" : "=f"(t) : "f"(x)); return t;
}
__device__ __forceinline__ float fsilu(float x) {
    float h = 0.5f * x;
    return fmaf(h, ftanh(h), h);
}

// ---------------- scratch ----------------
__device__ float g_q[NTOK*DIM];
__device__ float2 g_pbk[DIM*NTOK];    // [c][j] = {-0.5*pb, k}
__device__ float2 g_pvv[NTOK*DIM];    // [j][c] = {-0.5*pv, v}
__device__ float g_rv2T[DIM*DIM];     // [c][o]
__device__ u64   g_rb2d[DIM*NH];      // [c][h] duplicated pairs
__device__ float g_qkvT[DIM*3*DIM];   // [k][o]
__device__ float g_w1T[DIM*HIDN];     // [k][o]
__device__ float g_w2T[DIM*HIDN];
__device__ float g_w3T[HIDN*DIM];     // [o][d]
__device__ float g_scores[NTOK*NH*NTOK]; // [i][h][j]
__device__ float g_resid[NTOK*DIM];
__device__ float g_gate[NTOK*HIDN];

// ---------------- prep: P matrices (prescaled, interleaved) + rb2 dup ----------------
__global__ void prep_p(const float* __restrict__ coords,
                       const float* __restrict__ rb1_w,
                       const float* __restrict__ rv1_w,
                       const float* __restrict__ rb2_w) {
    int idx = blockIdx.x * 256 + threadIdx.x;   // 512 blocks -> 131072
    {
        int c = idx >> 9, n = idx & 511;        // [c][n]
        float x0 = coords[n*3+0], x1 = coords[n*3+1], x2 = coords[n*3+2];
        float pb = x0*rb1_w[c*3+0] + x1*rb1_w[c*3+1] + x2*rb1_w[c*3+2];
        g_pbk[idx].x = -0.5f * pb;
    }
    {
        int n = idx >> 8, c = idx & 255;        // [n][c]
        float x0 = coords[n*3+0], x1 = coords[n*3+1], x2 = coords[n*3+2];
        float pv = x0*rv1_w[c*3+0] + x1*rv1_w[c*3+1] + x2*rv1_w[c*3+2];
        g_pvv[idx].x = -0.5f * pv;
    }
    if (idx < NH*DIM) {
        int h = idx / DIM, c = idx % DIM;
        float r = rb2_w[idx];
        g_rb2d[c*NH + h] = pk2(r, r);
    }
}

// ---------------- tiled transposes ----------------
__global__ void tr_kernel(const float* __restrict__ qkv_w,
                          const float* __restrict__ rv2_w,
                          const float* __restrict__ w1,
                          const float* __restrict__ w2,
                          const float* __restrict__ w3) {
    __shared__ float tile[32][33];
    const float* src; float* dst; int R, C;
    switch (blockIdx.z) {
        case 0: src = qkv_w; dst = g_qkvT; R = 768; C = 256; break;
        case 1: src = rv2_w; dst = g_rv2T; R = 256; C = 256; break;
        case 2: src = w1;    dst = g_w1T;  R = HIDN; C = 256; break;
        case 3: src = w2;    dst = g_w2T;  R = HIDN; C = 256; break;
        default: src = w3;   dst = g_w3T;  R = 256; C = HIDN; break;
    }
    int bx = blockIdx.x * 32, by = blockIdx.y * 32;
    if (bx >= C || by >= R) return;
    int tx = threadIdx.x, ty = threadIdx.y;
    #pragma unroll
    for (int dy = ty; dy < 32; dy += 8) {
        int r = by + dy, cc = bx + tx;
        if (r < R && cc < C) tile[dy][tx] = src[r*C + cc];
    }
    __syncthreads();
    #pragma unroll
    for (int dy = ty; dy < 32; dy += 8) {
        int r = bx + dy, cc = by + tx;   // dst is [C][R]
        if (r < C && cc < R) dst[r*R + cc] = tile[tx][dy];
    }
}

// ---- in-block LayerNorm of 4 rows into xs[c] (float4 over rows) ----
__device__ __forceinline__ void block_ln4(const float* __restrict__ src, int i0,
                                          const float* __restrict__ lnw,
                                          const float* __restrict__ lnb,
                                          float4* xs, float2 (*red2)[4]) {
    int t = threadIdx.x;
    int lane = t & 31, r = t >> 7, wir = (t >> 5) & 3;
    int cc = (t & 127) * 2;
    float2 xv = *(const float2*)&src[(i0+r)*DIM + cc];
    float s1 = xv.x + xv.y;
    float s2 = fmaf(xv.x, xv.x, xv.y*xv.y);
    #pragma unroll
    for (int o = 16; o; o >>= 1) {
        s1 += __shfl_xor_sync(0xffffffffu, s1, o);
        s2 += __shfl_xor_sync(0xffffffffu, s2, o);
    }
    if (lane == 0) red2[r][wir] = make_float2(s1, s2);
    __syncthreads();
    float S1 = red2[r][0].x + red2[r][1].x + red2[r][2].x + red2[r][3].x;
    float S2 = red2[r][0].y + red2[r][1].y + red2[r][2].y + red2[r][3].y;
    float mean = S1 * (1.0f/256.0f);
    float var  = S2 * (1.0f/256.0f) - mean*mean;
    float inv  = rsqrtf(var + 1e-5f);
    float2 wv = *(const float2*)&lnw[cc];
    float2 bv = *(const float2*)&lnb[cc];
    ((float*)&xs[cc])[r]   = (xv.x - mean)*inv*wv.x + bv.x;
    ((float*)&xs[cc+1])[r] = (xv.y - mean)*inv*wv.y + bv.y;
    __syncthreads();
}

// ---------------- QKV (LN1 fused): 4 rows, 256-col chunk, 2 cols/thread, k-split 4 ----------------
__global__ __launch_bounds__(512) void qkv_kernel(const float* __restrict__ x,
                                                  const float* __restrict__ ln1_w,
                                                  const float* __restrict__ ln1_b,
                                                  const float* __restrict__ qkv_b) {
    __shared__ float4 xs[DIM];
    __shared__ float2 red2[4][4];
    __shared__ u64 part[128][3][4];
    int t = threadIdx.x;
    int i0 = blockIdx.x * 4, chunk = blockIdx.y;
    block_ln4(x, i0, ln1_w, ln1_b, xs, red2);

    int p = t & 127, kh = t >> 7;
    int ob = chunk*256 + p*2;
    u64 a0 = 0, a1 = 0, b0 = 0, b1 = 0;
    int kbeg = kh * 64;
    #pragma unroll 4
    for (int kk = 0; kk < 64; kk++) {
        int k = kbeg + kk;
        float2 w2 = *(const float2*)&g_qkvT[k*768 + ob];
        ulonglong2 xv = *(const ulonglong2*)&xs[k];
        u64 w0 = pk2(w2.x, w2.x), w1 = pk2(w2.y, w2.y);
        a0 = fma2(xv.x, w0, a0); a1 = fma2(xv.y, w0, a1);
        b0 = fma2(xv.x, w1, b0); b1 = fma2(xv.y, w1, b1);
    }
    if (kh) { part[p][kh-1][0]=a0; part[p][kh-1][1]=a1; part[p][kh-1][2]=b0; part[p][kh-1][3]=b1; }
    __syncthreads();
    if (kh == 0) {
        #pragma unroll
        for (int m = 0; m < 3; m++) {
            a0 = add2(a0, part[p][m][0]); a1 = add2(a1, part[p][m][1]);
            b0 = add2(b0, part[p][m][2]); b1 = add2(b1, part[p][m][3]);
        }
        float2 bb = *(const float2*)&qkv_b[ob];
        float2 A = up2(a0), B = up2(a1), C = up2(b0), D = up2(b1);
        float r0[4] = { A.x+bb.x, A.y+bb.x, B.x+bb.x, B.y+bb.x };
        float r1[4] = { C.x+bb.y, C.y+bb.y, D.x+bb.y, D.y+bb.y };
        if (chunk == 0) {
            #pragma unroll
            for (int rr = 0; rr < 4; rr++) {
                g_q[(i0+rr)*DIM + ob]   = r0[rr];
                g_q[(i0+rr)*DIM + ob+1] = r1[rr];
            }
        } else if (chunk == 1) {
            int c0 = ob - 256;
            #pragma unroll
            for (int rr = 0; rr < 4; rr++) {
                ((float*)g_pbk)[(c0*NTOK + i0+rr)*2 + 1]     = r0[rr];
                ((float*)g_pbk)[((c0+1)*NTOK + i0+rr)*2 + 1] = r1[rr];
            }
        } else {
            int c0 = ob - 512;
            #pragma unroll
            for (int rr = 0; rr < 4; rr++) {
                ((float*)g_pvv)[((i0+rr)*DIM + c0)*2 + 1]   = r0[rr];
                ((float*)g_pvv)[((i0+rr)*DIM + c0+1)*2 + 1] = r1[rr];
            }
        }
    }
}

// ---------------- scores: 2 i x 256 j per block, i-packed bias ----------------
__global__ __launch_bounds__(256, 4) void scores_kernel(const float* __restrict__ rb1_b,
                                                        const float* __restrict__ rb2_b) {
    __shared__ u64 pbq[DIM][2];
    __shared__ u64 rbs[DIM*NH];
    int i0 = (blockIdx.x >> 1) * 2;
    int t = threadIdx.x;
    int j = (blockIdx.x & 1) * 256 + t;

    {
        float bh = 0.5f * rb1_b[t];
        float p0 = bh - g_pbk[t*NTOK + i0].x;
        float p1 = bh - g_pbk[t*NTOK + i0 + 1].x;
        pbq[t][0] = pk2(p0, p1);
        pbq[t][1] = pk2(g_q[i0*DIM + t], g_q[(i0+1)*DIM + t]);
    }
    #pragma unroll
    for (int m = 0; m < 8; m++) rbs[m*256 + t] = g_rb2d[m*256 + t];
    __syncthreads();

    u64 accb[8] = {}, accs[8] = {};
    #pragma unroll
    for (int h = 0; h < NH; h++) {
        #pragma unroll 4
        for (int c32 = 0; c32 < 32; c32++) {
            int c = h*32 + c32;
            float2 pkv = g_pbk[c*NTOK + j];
            u64 pbn = pk2(pkv.x, pkv.x);
            u64 kd  = pk2(pkv.y, pkv.y);
            ulonglong2 pq = *(const ulonglong2*)&pbq[c][0];
            u64 h2 = add2(pq.x, pbn);
            float2 sh = up2(h2);
            u64 t2 = pk2(ftanh(sh.x), ftanh(sh.y));
            u64 hb2 = fma2(h2, t2, h2);
            ulonglong2 rA = *(const ulonglong2*)&rbs[c*8 + 0];
            ulonglong2 rB = *(const ulonglong2*)&rbs[c*8 + 2];
            ulonglong2 rC = *(const ulonglong2*)&rbs[c*8 + 4];
            ulonglong2 rD = *(const ulonglong2*)&rbs[c*8 + 6];
            accb[0] = fma2(hb2, rA.x, accb[0]); accb[1] = fma2(hb2, rA.y, accb[1]);
            accb[2] = fma2(hb2, rB.x, accb[2]); accb[3] = fma2(hb2, rB.y, accb[3]);
            accb[4] = fma2(hb2, rC.x, accb[4]); accb[5] = fma2(hb2, rC.y, accb[5]);
            accb[6] = fma2(hb2, rD.x, accb[6]); accb[7] = fma2(hb2, rD.y, accb[7]);
            accs[h] = fma2(pq.y, kd, accs[h]);
        }
    }
    const float sc = 0.17677669529663687f;
    #pragma unroll
    for (int h = 0; h < NH; h++) {
        float2 b = up2(accb[h]);
        float2 qk = up2(accs[h]);
        float rbb = rb2_b[h];
        g_scores[(i0*NH + h)*NTOK + j]     = fmaf(qk.x, sc, b.x + rbb);
        g_scores[((i0+1)*NH + h)*NTOK + j] = fmaf(qk.y, sc, b.y + rbb);
    }
}

// ---------------- attention ----------------
__global__ __launch_bounds__(256, 4) void attn_kernel(const float* __restrict__ x,
                                                      const float* __restrict__ rv1_b,
                                                      const float* __restrict__ rv2_b) {
    __shared__ float wT[NTOK*12];
    __shared__ float whid[NH*DIM];
    __shared__ float sinv[NH];
    int i = blockIdx.x, t = threadIdx.x;
    int wid = t >> 5, lane = t & 31;

    {
        const float* row = g_scores + (i*NH + wid)*NTOK;
        float m = -1e30f;
        for (int jj = lane; jj < NTOK; jj += 32) m = fmaxf(m, row[jj]);
        #pragma unroll
        for (int o = 16; o; o >>= 1) m = fmaxf(m, __shfl_xor_sync(0xffffffffu, m, o));
        float s = 0.f;
        for (int jj = lane; jj < NTOK; jj += 32) {
            float e = __expf(row[jj] - m);
            wT[jj*12 + wid] = e;
            s += e;
        }
        #pragma unroll
        for (int o = 16; o; o >>= 1) s += __shfl_xor_sync(0xffffffffu, s, o);
        if (lane == 0) sinv[wid] = __fdividef(1.0f, s);
    }
    __syncthreads();

    float pvih = 0.5f*rv1_b[t] - g_pvv[i*DIM + t].x;
    int hs = t >> 5;
    u64 accW[4] = {};
    float accC = 0.f;
    #pragma unroll 2
    for (int j = 0; j < NTOK; j++) {
        float2 pv = g_pvv[j*DIM + t];
        ulonglong2 wA = *(const ulonglong2*)&wT[j*12];
        ulonglong2 wB = *(const ulonglong2*)&wT[j*12 + 4];
        float hin = pvih + pv.x;
        float hv = fmaf(hin, ftanh(hin), hin);
        u64 hh = pk2(hv, hv);
        accW[0] = fma2(hh, wA.x, accW[0]); accW[1] = fma2(hh, wA.y, accW[1]);
        accW[2] = fma2(hh, wB.x, accW[2]); accW[3] = fma2(hh, wB.y, accW[3]);
        accC += wT[j*12 + hs] * pv.y;
    }
    #pragma unroll
    for (int hp = 0; hp < 4; hp++) {
        float2 v = up2(accW[hp]);
        whid[(2*hp)*DIM + t]   = v.x * sinv[2*hp];
        whid[(2*hp+1)*DIM + t] = v.y * sinv[2*hp+1];
    }
    accC *= sinv[hs];
    __syncthreads();

    float accP = 0.f;
    #pragma unroll 4
    for (int c = 0; c < DIM; c++)
        accP += whid[hs*DIM + c] * g_rv2T[c*DIM + t];

    g_resid[i*DIM + t] = x[i*DIM + t] + accC + accP + rv2_b[t];
}

// ---------------- FFN up (LN2 fused): 4 rows, 2 cols/thread, k-split 4 ----------------
__global__ __launch_bounds__(512) void ffn1_kernel(const float* __restrict__ ln2_w,
                                                   const float* __restrict__ ln2_b,
                                                   const float* __restrict__ b1,
                                                   const float* __restrict__ b2) {
    __shared__ float4 xs[DIM];
    __shared__ float2 red2[4][4];
    __shared__ u64 parta[128][3][4];
    __shared__ u64 partc[128][3][4];
    int t = threadIdx.x;
    int i0 = blockIdx.x * 4, chunk = blockIdx.y;
    block_ln4(g_resid, i0, ln2_w, ln2_b, xs, red2);

    int p = t & 127, kh = t >> 7;
    int o = chunk*256 + p*2;
    int ocl = (o <= HIDN-2) ? o : (HIDN-2);
    u64 a0=0, a1=0, a2=0, a3=0, c0=0, c1=0, c2=0, c3=0;
    int kbeg = kh * 64;
    #pragma unroll 4
    for (int kk = 0; kk < 64; kk++) {
        int k = kbeg + kk;
        float2 u2 = *(const float2*)&g_w1T[k*HIDN + ocl];
        float2 v2 = *(const float2*)&g_w2T[k*HIDN + ocl];
        ulonglong2 xv = *(const ulonglong2*)&xs[k];
        u64 u0 = pk2(u2.x,u2.x), u1 = pk2(u2.y,u2.y);
        u64 v0 = pk2(v2.x,v2.x), v1 = pk2(v2.y,v2.y);
        a0 = fma2(xv.x,u0,a0); a1 = fma2(xv.y,u0,a1);
        a2 = fma2(xv.x,u1,a2); a3 = fma2(xv.y,u1,a3);
        c0 = fma2(xv.x,v0,c0); c1 = fma2(xv.y,v0,c1);
        c2 = fma2(xv.x,v1,c2); c3 = fma2(xv.y,v1,c3);
    }
    if (kh) {
        parta[p][kh-1][0]=a0; parta[p][kh-1][1]=a1; parta[p][kh-1][2]=a2; parta[p][kh-1][3]=a3;
        partc[p][kh-1][0]=c0; partc[p][kh-1][1]=c1; partc[p][kh-1][2]=c2; partc[p][kh-1][3]=c3;
    }
    __syncthreads();
    if (kh == 0 && o < HIDN) {
        #pragma unroll
        for (int m = 0; m < 3; m++) {
            a0 = add2(a0, parta[p][m][0]); a1 = add2(a1, parta[p][m][1]);
            a2 = add2(a2, parta[p][m][2]); a3 = add2(a3, parta[p][m][3]);
            c0 = add2(c0, partc[p][m][0]); c1 = add2(c1, partc[p][m][1]);
            c2 = add2(c2, partc[p][m][2]); c3 = add2(c3, partc[p][m][3]);
        }
        float2 A0 = up2(a0), A1 = up2(a1), A2 = up2(a2), A3 = up2(a3);
        float2 C0 = up2(c0), C1 = up2(c1), C2 = up2(c2), C3 = up2(c3);
        float bb10 = b1[o], bb11 = b1[o+1], bb20 = b2[o], bb21 = b2[o+1];
        g_gate[(i0+0)*HIDN + o]   = fsilu(A0.x + bb10) * (C0.x + bb20);
        g_gate[(i0+1)*HIDN + o]   = fsilu(A0.y + bb10) * (C0.y + bb20);
        g_gate[(i0+2)*HIDN + o]   = fsilu(A1.x + bb10) * (C1.x + bb20);
        g_gate[(i0+3)*HIDN + o]   = fsilu(A1.y + bb10) * (C1.y + bb20);
        g_gate[(i0+0)*HIDN + o+1] = fsilu(A2.x + bb11) * (C2.x + bb21);
        g_gate[(i0+1)*HIDN + o+1] = fsilu(A2.y + bb11) * (C2.y + bb21);
        g_gate[(i0+2)*HIDN + o+1] = fsilu(A3.x + bb11) * (C3.x + bb21);
        g_gate[(i0+3)*HIDN + o+1] = fsilu(A3.y + bb11) * (C3.y + bb21);
    }
}

// ---------------- FFN down + residual: 2 rows, 2 cols/thread, o-split 4 ----------------
__global__ __launch_bounds__(512) void ffn2_kernel(const float* __restrict__ b3,
                                                   float* __restrict__ out) {
    __shared__ float2 gs[HIDN];
    __shared__ u64 part[128][3][2];
    int i0 = blockIdx.x * 2, t = threadIdx.x;
    int p = t & 127, oh = t >> 7;
    for (int idx = t; idx < HIDN; idx += 512)
        gs[idx] = make_float2(g_gate[i0*HIDN + idx], g_gate[(i0+1)*HIDN + idx]);
    __syncthreads();
    const int obeg[5] = {0, 171, 342, 512, 682};
    int os = obeg[oh], oe = obeg[oh+1];
    int d = p*2;
    u64 acc0 = 0, acc1 = 0;
    for (int o = os; o < oe; o++) {
        float2 w = *(const float2*)&g_w3T[o*DIM + d];
        u64 g2 = *(const u64*)&gs[o];
        acc0 = fma2(g2, pk2(w.x, w.x), acc0);
        acc1 = fma2(g2, pk2(w.y, w.y), acc1);
    }
    if (oh) { part[p][oh-1][0] = acc0; part[p][oh-1][1] = acc1; }
    __syncthreads();
    if (oh == 0) {
        #pragma unroll
        for (int m = 0; m < 3; m++) {
            acc0 = add2(acc0, part[p][m][0]);
            acc1 = add2(acc1, part[p][m][1]);
        }
        float2 A = up2(acc0), B = up2(acc1);
        float2 bb = *(const float2*)&b3[d];
        out[i0*DIM + d]       = g_resid[i0*DIM + d]       + A.x + bb.x;
        out[(i0+1)*DIM + d]   = g_resid[(i0+1)*DIM + d]   + A.y + bb.x;
        out[i0*DIM + d+1]     = g_resid[i0*DIM + d+1]     + B.x + bb.y;
        out[(i0+1)*DIM + d+1] = g_resid[(i0+1)*DIM + d+1] + B.y + bb.y;
    }
}

// ---------------- launch ----------------
extern "C" void kernel_launch(void* const* d_in, const int* in_sizes, int n_in,
                              void* d_out, int out_size) {
    const float* x      = (const float*)d_in[0];
    const float* coords = (const float*)d_in[1];
    const float* ln1_w  = (const float*)d_in[2];
    const float* ln1_b  = (const float*)d_in[3];
    const float* ln2_w  = (const float*)d_in[4];
    const float* ln2_b  = (const float*)d_in[5];
    const float* qkv_w  = (const float*)d_in[6];
    const float* qkv_b  = (const float*)d_in[7];
    const float* rb1_w  = (const float*)d_in[8];
    const float* rb1_b  = (const float*)d_in[9];
    const float* rb2_w  = (const float*)d_in[10];
    const float* rb2_b  = (const float*)d_in[11];
    const float* rv1_w  = (const float*)d_in[12];
    const float* rv1_b  = (const float*)d_in[13];
    const float* rv2_w  = (const float*)d_in[14];
    const float* rv2_b  = (const float*)d_in[15];
    const float* w1     = (const float*)d_in[16];
    const float* b1     = (const float*)d_in[17];
    const float* w2     = (const float*)d_in[18];
    const float* b2     = (const float*)d_in[19];
    const float* w3     = (const float*)d_in[20];
    const float* b3     = (const float*)d_in[21];
    float* out = (float*)d_out;

    prep_p<<<512, 256>>>(coords, rb1_w, rv1_w, rb2_w);
    tr_kernel<<<dim3(22, 24, 5), dim3(32, 8)>>>(qkv_w, rv2_w, w1, w2, w3);
    qkv_kernel<<<dim3(128, 3), 512>>>(x, ln1_w, ln1_b, qkv_b);
    scores_kernel<<<NTOK, 256>>>(rb1_b, rb2_b);
    attn_kernel<<<NTOK, 256>>>(x, rv1_b, rv2_b);
    ffn1_kernel<<<dim3(128, 3), 512>>>(ln2_w, ln2_b, b1, b2);
    ffn2_kernel<<<256, 512>>>(b3, out);
}